// round 9
// baseline (speedup 1.0000x reference)
#include <cuda_runtime.h>
#include <cuda_bf16.h>
#include <cstdint>

#define NN 1024
#define BB 64
#define CC 128
#define HH 64
#define ED 16
#define BCDIM (BB*CC)   /* 8192 */

// ---------------------------------------------------------------------------
// Device-global scratch
__device__ float g_X  [NN*BCDIM];                  // 32 MB concat(x,state) [n, b*128+c]
__device__ float g_X2s[NN*BB*HH];                  // 16 MB z*state compact [n, b*64+c]
__device__ float g_Y  [2*NN*BCDIM];                // 64 MB [A@X ; A^2@X]
__device__ float g_Ys [2*NN*BB*HH];                // 32 MB phase-2 state-half results
__device__ float g_R  [NN*BB*HH];                  // 16 MB r gate
__device__ __nv_bfloat16 g_Ah [2*NN*NN];           // rows 0-1023: A hi; 1024-2047: A^2 hi
__device__ __nv_bfloat16 g_Al [2*NN*NN];
__device__ __nv_bfloat16 g_Ath[NN*NN];
__device__ __nv_bfloat16 g_Atl[NN*NN];
__device__ __nv_bfloat16 g_Bt1[(size_t)BCDIM*NN];
__device__ __nv_bfloat16 g_Bt2[(size_t)BCDIM*NN];
__device__ __nv_bfloat16 g_Wh [(size_t)NN*3*CC*CC];   // gate weights hi
__device__ __nv_bfloat16 g_Wl [(size_t)NN*3*CC*CC];   // gate weights lo
__device__ __nv_bfloat16 g_Whu[(size_t)NN*3*CC*HH];   // upd weights hi
__device__ __nv_bfloat16 g_Wlu[(size_t)NN*3*CC*HH];   // upd weights lo

// ---------------------------------------------------------------------------
// Streams/events for graph-fork
struct ForkCtx {
    cudaStream_t s1, s2;
    cudaEvent_t fork, eA0, eA, eWg, eWu;
    ForkCtx() {
        cudaStreamCreateWithFlags(&s1, cudaStreamNonBlocking);
        cudaStreamCreateWithFlags(&s2, cudaStreamNonBlocking);
        cudaEventCreateWithFlags(&fork, cudaEventDisableTiming);
        cudaEventCreateWithFlags(&eA0,  cudaEventDisableTiming);
        cudaEventCreateWithFlags(&eA,   cudaEventDisableTiming);
        cudaEventCreateWithFlags(&eWg,  cudaEventDisableTiming);
        cudaEventCreateWithFlags(&eWu,  cudaEventDisableTiming);
    }
};
static ForkCtx g_fork;

// ---------------------------------------------------------------------------
// PTX helpers (sm_80-baseline only)
__device__ __forceinline__ uint32_t smem_to_u32(const void* p) {
    uint32_t a;
    asm("{ .reg .u64 t; cvta.to.shared.u64 t, %1; cvt.u32.u64 %0, t; }"
        : "=r"(a) : "l"(p));
    return a;
}
__device__ __forceinline__ void cp_async16(uint32_t dst, const void* src) {
    asm volatile("cp.async.cg.shared.global [%0], [%1], 16;" :: "r"(dst), "l"(src));
}
#define CP_COMMIT() asm volatile("cp.async.commit_group;" ::: "memory")

__device__ __forceinline__ void ldsm_x4(uint32_t* r, uint32_t addr) {
    asm volatile("ldmatrix.sync.aligned.m8n8.x4.shared.b16 {%0,%1,%2,%3}, [%4];"
        : "=r"(r[0]), "=r"(r[1]), "=r"(r[2]), "=r"(r[3]) : "r"(addr));
}
__device__ __forceinline__ void ldsm_x4_t(uint32_t* r, uint32_t addr) {
    asm volatile("ldmatrix.sync.aligned.m8n8.x4.trans.shared.b16 {%0,%1,%2,%3}, [%4];"
        : "=r"(r[0]), "=r"(r[1]), "=r"(r[2]), "=r"(r[3]) : "r"(addr));
}
__device__ __forceinline__ void mma16816(float* d, const uint32_t* a, const uint32_t* b) {
    asm volatile(
        "mma.sync.aligned.m16n8k16.row.col.f32.bf16.bf16.f32 "
        "{%0,%1,%2,%3}, {%4,%5,%6,%7}, {%8,%9}, {%0,%1,%2,%3};"
        : "+f"(d[0]), "+f"(d[1]), "+f"(d[2]), "+f"(d[3])
        : "r"(a[0]), "r"(a[1]), "r"(a[2]), "r"(a[3]), "r"(b[0]), "r"(b[1]));
}
__device__ __forceinline__ void split_store(char* base_h, char* base_l,
                                            int byteoff, float4 v) {
    __nv_bfloat16 h[4], l[4];
    float vv[4] = {v.x, v.y, v.z, v.w};
#pragma unroll
    for (int k = 0; k < 4; k++) {
        h[k] = __float2bfloat16(vv[k]);
        l[k] = __float2bfloat16(vv[k] - __bfloat162float(h[k]));
    }
    *(uint2*)(base_h + byteoff) = *(uint2*)h;
    *(uint2*)(base_l + byteoff) = *(uint2*)l;
}
__device__ __forceinline__ uint32_t pack_split2(float a, float b, uint32_t* lo) {
    __nv_bfloat16 h0 = __float2bfloat16(a);
    __nv_bfloat16 h1 = __float2bfloat16(b);
    __nv_bfloat16 l0 = __float2bfloat16(a - __bfloat162float(h0));
    __nv_bfloat16 l1 = __float2bfloat16(b - __bfloat162float(h1));
    uint32_t hi;
    ((__nv_bfloat16*)&hi)[0] = h0; ((__nv_bfloat16*)&hi)[1] = h1;
    ((__nv_bfloat16*)lo)[0] = l0;  ((__nv_bfloat16*)lo)[1] = l1;
    return hi;
}

// ---------------------------------------------------------------------------
// Fused: build X[n, b*128+c] = concat(x,state)[b,n,c]  AND  Bt[bc, n] hi/lo split
__global__ void build_X_fused_kernel(const float* __restrict__ x,
                                     const float* __restrict__ st,
                                     float* __restrict__ X,
                                     __nv_bfloat16* __restrict__ hi,
                                     __nv_bfloat16* __restrict__ lo) {
    __shared__ float t[32][33];
    int bc0 = blockIdx.x * 32;
    int n0  = blockIdx.y * 32;
    int tx = threadIdx.x, ty = threadIdx.y;
#pragma unroll
    for (int i = 0; i < 4; i++) {
        int n = n0 + ty + 8*i;
        int bc = bc0 + tx;
        int c = bc & 127, b = bc >> 7;
        float v = (c < HH) ? x [(size_t)b * (NN*HH) + n*HH + c]
                           : st[(size_t)b * (NN*HH) + n*HH + (c - HH)];
        X[(size_t)n * BCDIM + bc] = v;
        t[ty + 8*i][tx] = v;
    }
    __syncthreads();
#pragma unroll
    for (int i = 0; i < 4; i++) {
        float v = t[tx][ty + 8*i];
        __nv_bfloat16 h = __float2bfloat16(v);
        size_t o = (size_t)(bc0 + ty + 8*i) * NN + n0 + tx;
        hi[o] = h;
        lo[o] = __float2bfloat16(v - __bfloat162float(h));
    }
}

// ---------------------------------------------------------------------------
__global__ void compute_A_kernel(const float* __restrict__ E,
                                 __nv_bfloat16* __restrict__ Ah,
                                 __nv_bfloat16* __restrict__ Al,
                                 __nv_bfloat16* __restrict__ Ath,
                                 __nv_bfloat16* __restrict__ Atl) {
    int i = blockIdx.x;
    int tid = threadIdx.x;
    __shared__ float Ei[ED];
    __shared__ float red[256];
    if (tid < ED) Ei[tid] = E[i*ED + tid];
    __syncthreads();

    float v[4];
    float vmax = 0.0f;
#pragma unroll
    for (int p = 0; p < 4; p++) {
        int j = tid + p * 256;
        const float4* Ej = (const float4*)(E + (size_t)j * ED);
        float4 e0 = Ej[0], e1 = Ej[1], e2 = Ej[2], e3 = Ej[3];
        float d = Ei[0]*e0.x + Ei[1]*e0.y + Ei[2]*e0.z + Ei[3]*e0.w
                + Ei[4]*e1.x + Ei[5]*e1.y + Ei[6]*e1.z + Ei[7]*e1.w
                + Ei[8]*e2.x + Ei[9]*e2.y + Ei[10]*e2.z + Ei[11]*e2.w
                + Ei[12]*e3.x + Ei[13]*e3.y + Ei[14]*e3.z + Ei[15]*e3.w;
        d = fmaxf(d, 0.0f);
        v[p] = d;
        vmax = fmaxf(vmax, d);
    }
    red[tid] = vmax; __syncthreads();
    for (int s = 128; s > 0; s >>= 1) {
        if (tid < s) red[tid] = fmaxf(red[tid], red[tid + s]);
        __syncthreads();
    }
    vmax = red[0];
    __syncthreads();
    float lsum = 0.0f;
#pragma unroll
    for (int p = 0; p < 4; p++) { v[p] = __expf(v[p] - vmax); lsum += v[p]; }
    red[tid] = lsum; __syncthreads();
    for (int s = 128; s > 0; s >>= 1) {
        if (tid < s) red[tid] += red[tid + s];
        __syncthreads();
    }
    float inv = 1.0f / red[0];
#pragma unroll
    for (int p = 0; p < 4; p++) {
        int j = tid + p * 256;
        float a = v[p] * inv;
        __nv_bfloat16 h = __float2bfloat16(a);
        __nv_bfloat16 l = __float2bfloat16(a - __bfloat162float(h));
        Ah [(size_t)i * NN + j] = h;
        Al [(size_t)i * NN + j] = l;
        Ath[(size_t)j * NN + i] = h;
        Atl[(size_t)j * NN + i] = l;
    }
}

// ---------------------------------------------------------------------------
// transpose + split: src fp32 [NN, W] -> hi/lo bf16 [W, NN]
__global__ void transpose_split_kernel(const float* __restrict__ src,
                                       __nv_bfloat16* __restrict__ hi,
                                       __nv_bfloat16* __restrict__ lo, int W) {
    __shared__ float t[32][33];
    int m0 = blockIdx.x * 32;
    int n0 = blockIdx.y * 32;
    int tx = threadIdx.x, ty = threadIdx.y;
#pragma unroll
    for (int i = 0; i < 4; i++)
        t[ty + 8*i][tx] = src[(size_t)(n0 + ty + 8*i) * W + m0 + tx];
    __syncthreads();
#pragma unroll
    for (int i = 0; i < 4; i++) {
        float v = t[tx][ty + 8*i];
        __nv_bfloat16 h = __float2bfloat16(v);
        size_t o = (size_t)(m0 + ty + 8*i) * NN + n0 + tx;
        hi[o] = h;
        lo[o] = __float2bfloat16(v - __bfloat162float(h));
    }
}

// ---------------------------------------------------------------------------
// Big bf16x3 GEMM: C = (Ahi+Alo) @ (Bhi+Blo)^T. If Ch != nullptr, output is
// written as bf16 hi/lo split instead of fp32 C.
#define GSTRIDE 144
#define HALF_BYTES (128*GSTRIDE)
#define STAGE_BYTES (4*HALF_BYTES)
#define GEMM_SMEM (2*STAGE_BYTES)

__global__ __launch_bounds__(256, 1)
void mma_gemm_kernel(const __nv_bfloat16* __restrict__ Ahi,
                     const __nv_bfloat16* __restrict__ Alo,
                     const __nv_bfloat16* __restrict__ Bhi,
                     const __nv_bfloat16* __restrict__ Blo,
                     float* __restrict__ C,
                     __nv_bfloat16* __restrict__ Ch,
                     __nv_bfloat16* __restrict__ Cl,
                     int M, int N, int K) {
    extern __shared__ char smem[];
    uint32_t sb = smem_to_u32(smem);
    int tid = threadIdx.x;
    int lane = tid & 31, wid = tid >> 5;
    int wm = (wid >> 1) * 32;
    int wn = (wid & 1) * 64;
    int block_row = blockIdx.y * 128;
    int block_col = blockIdx.x * 128;

    const char* gA0 = (const char*)(Ahi + (size_t)block_row * K);
    const char* gA1 = (const char*)(Alo + (size_t)block_row * K);
    const char* gB0 = (const char*)(Bhi + (size_t)block_col * K);
    const char* gB1 = (const char*)(Blo + (size_t)block_col * K);

    int lr_ = tid >> 3;
    int lc_ = (tid & 7) * 16;

    float acc[2][8][4];
#pragma unroll
    for (int mt = 0; mt < 2; mt++)
#pragma unroll
        for (int nt = 0; nt < 8; nt++)
#pragma unroll
            for (int q = 0; q < 4; q++) acc[mt][nt][q] = 0.0f;

    int g = lane >> 3;
    int lr8 = lane & 7;
    int a_row = wm + (g & 1) * 8 + lr8;
    int a_kc  = (g >> 1) * 8;
    int b_row = wn + (g >> 1) * 8 + lr8;
    int b_kc  = (g & 1) * 8;

    int nstages = K >> 6;

    auto load_stage = [&](int st, int kt) {
        uint32_t base = sb + st * STAGE_BYTES;
        size_t k0b = (size_t)(kt * 64) * 2;
#pragma unroll
        for (int q = 0; q < 4; q++) {
            int r = lr_ + q * 32;
            uint32_t so = (uint32_t)(r * GSTRIDE + lc_);
            size_t go = (size_t)r * (K * 2) + k0b + lc_;
            cp_async16(base + 0*HALF_BYTES + so, gA0 + go);
            cp_async16(base + 1*HALF_BYTES + so, gA1 + go);
            cp_async16(base + 2*HALF_BYTES + so, gB0 + go);
            cp_async16(base + 3*HALF_BYTES + so, gB1 + go);
        }
        CP_COMMIT();
    };

    load_stage(0, 0);

    for (int kt = 0; kt < nstages; kt++) {
        int st = kt & 1;
        if (kt + 1 < nstages) {
            load_stage(st ^ 1, kt + 1);
            asm volatile("cp.async.wait_group 1;" ::: "memory");
        } else {
            asm volatile("cp.async.wait_group 0;" ::: "memory");
        }
        __syncthreads();

        uint32_t aHiB = sb + st * STAGE_BYTES;
        uint32_t aLoB = aHiB + HALF_BYTES;
        uint32_t bHiB = aLoB + HALF_BYTES;
        uint32_t bLoB = bHiB + HALF_BYTES;

#pragma unroll
        for (int ks = 0; ks < 4; ks++) {
            int kc = ks * 16;
            uint32_t ahi[2][4], alo[2][4];
#pragma unroll
            for (int mt = 0; mt < 2; mt++) {
                uint32_t ad = (uint32_t)((a_row + mt*16) * GSTRIDE + (kc + a_kc) * 2);
                ldsm_x4(ahi[mt], aHiB + ad);
                ldsm_x4(alo[mt], aLoB + ad);
            }
            uint32_t bhi[8][2], blo[8][2];
#pragma unroll
            for (int np = 0; np < 4; np++) {
                uint32_t bd = (uint32_t)((b_row + np*16) * GSTRIDE + (kc + b_kc) * 2);
                uint32_t t[4];
                ldsm_x4(t, bHiB + bd);
                bhi[2*np][0] = t[0]; bhi[2*np][1] = t[1];
                bhi[2*np+1][0] = t[2]; bhi[2*np+1][1] = t[3];
                ldsm_x4(t, bLoB + bd);
                blo[2*np][0] = t[0]; blo[2*np][1] = t[1];
                blo[2*np+1][0] = t[2]; blo[2*np+1][1] = t[3];
            }
#pragma unroll
            for (int mt = 0; mt < 2; mt++)
#pragma unroll
                for (int nt = 0; nt < 8; nt++) {
                    mma16816(acc[mt][nt], ahi[mt], bhi[nt]);
                    mma16816(acc[mt][nt], ahi[mt], blo[nt]);
                    mma16816(acc[mt][nt], alo[mt], bhi[nt]);
                }
        }
        __syncthreads();
    }

    int erow = lane >> 2, ecol = (lane & 3) * 2;
    if (Ch) {
#pragma unroll
        for (int mt = 0; mt < 2; mt++) {
            size_t r0 = (size_t)block_row + wm + mt*16 + erow;
#pragma unroll
            for (int nt = 0; nt < 8; nt++) {
                size_t cc = (size_t)block_col + wn + nt*8 + ecol;
                uint32_t lo0, lo1;
                uint32_t hi0 = pack_split2(acc[mt][nt][0], acc[mt][nt][1], &lo0);
                uint32_t hi1 = pack_split2(acc[mt][nt][2], acc[mt][nt][3], &lo1);
                *(uint32_t*)(Ch + r0 * N + cc)       = hi0;
                *(uint32_t*)(Cl + r0 * N + cc)       = lo0;
                *(uint32_t*)(Ch + (r0 + 8) * N + cc) = hi1;
                *(uint32_t*)(Cl + (r0 + 8) * N + cc) = lo1;
            }
        }
    } else {
#pragma unroll
        for (int mt = 0; mt < 2; mt++) {
            size_t r0 = (size_t)block_row + wm + mt*16 + erow;
#pragma unroll
            for (int nt = 0; nt < 8; nt++) {
                size_t cc = (size_t)block_col + wn + nt*8 + ecol;
                *(float2*)(C + r0 * N + cc)       = make_float2(acc[mt][nt][0], acc[mt][nt][1]);
                *(float2*)(C + (r0 + 8) * N + cc) = make_float2(acc[mt][nt][2], acc[mt][nt][3]);
            }
        }
    }
}

// ---------------------------------------------------------------------------
// W[n,:] = sum_e E[n,e] * Wp[e,:], output bf16 hi/lo
__global__ __launch_bounds__(256)
void build_W_kernel(const float* __restrict__ Wp,
                    const float* __restrict__ E,
                    __nv_bfloat16* __restrict__ Wh,
                    __nv_bfloat16* __restrict__ Wl, int TC) {
    int ng = blockIdx.y;
    int cbase = blockIdx.x * 1024;
    __shared__ float Es[16][16];
    {
        int nn = threadIdx.x >> 4, e = threadIdx.x & 15;
        if (threadIdx.x < 256) Es[nn][e] = E[(ng * 16 + nn) * ED + e];
    }
    __syncthreads();
#pragma unroll 1
    for (int cc = 0; cc < 1024; cc += 256) {
        int c = cbase + cc + threadIdx.x;
        float wp[16];
#pragma unroll
        for (int e = 0; e < 16; e++) wp[e] = Wp[(size_t)e * TC + c];
#pragma unroll
        for (int nn = 0; nn < 16; nn++) {
            float a = 0.0f;
#pragma unroll
            for (int e = 0; e < 16; e++) a += Es[nn][e] * wp[e];
            __nv_bfloat16 h = __float2bfloat16(a);
            size_t o = (size_t)(ng * 16 + nn) * TC + c;
            Wh[o] = h;
            Wl[o] = __float2bfloat16(a - __bfloat162float(h));
        }
    }
}

// ---------------------------------------------------------------------------
// Per-node GATE via mma.sync bf16x3, double-buffered pipeline.
// smem stages of 53248B: XH +0 (64x144), XL +9216, WH +18432 (64x272), WL +35840.
#define GATE_STAGE 53248
#define GATE_SMEM  (2*GATE_STAGE + 512)
__global__ __launch_bounds__(256)
void pernode_gate_mma(const float* __restrict__ X, const float* __restrict__ Y,
                      const __nv_bfloat16* __restrict__ Wh,
                      const __nv_bfloat16* __restrict__ Wl,
                      const float* __restrict__ E, const float* __restrict__ bpool,
                      float* __restrict__ X2s, float* __restrict__ R) {
    extern __shared__ char sm[];
    uint32_t sb = smem_to_u32(sm);
    float* bias = (float*)(sm + 2*GATE_STAGE);
    int n = blockIdx.x;
    int tid = threadIdx.x, lane = tid & 31, wid = tid >> 5;

    if (tid < 128) {
        float a = 0.0f;
#pragma unroll
        for (int e = 0; e < 16; e++) a += E[n*ED + e] * bpool[e*128 + tid];
        bias[tid] = a;
    }

    const float* Xn  = X + (size_t)n * BCDIM;
    const float* Y1p = Y + (size_t)n * BCDIM;
    const float* Y2p = Y + (size_t)(NN + n) * BCDIM;
    const __nv_bfloat16* gWh = Wh + (size_t)n * (3*CC*CC);
    const __nv_bfloat16* gWl = Wl + (size_t)n * (3*CC*CC);

    int wm = (wid >> 1) * 16, wn = (wid & 1) * 64;
    int g = lane >> 3, lr8 = lane & 7;
    int cr = tid >> 2;
    int ccol = (tid & 3) * 16;

    // W-chunk async loader into stage st
    auto loadW = [&](int st, int ck) {
        int kc0 = ck * 64;
        uint32_t base = sb + st * GATE_STAGE;
#pragma unroll
        for (int q = 0; q < 4; q++) {
            int m = tid + q * 256;
            int kr = m >> 4, o8 = m & 15;
            uint32_t so = (uint32_t)(kr * 272 + o8 * 16);
            size_t eoff = (size_t)(kc0 + kr) * 128 + o8 * 8;
            cp_async16(base + 18432 + so, gWh + eoff);
            cp_async16(base + 35840 + so, gWl + eoff);
        }
        CP_COMMIT();
    };
    // X-chunk fetch into regs
    auto loadX = [&](int ck, float4* xv) {
        const float* p1;
        const float* p2 = nullptr;
        switch (ck) {
            case 0: p1 = Xn;        break;
            case 1: p1 = Xn + 64;   break;
            case 2: p1 = Y1p;       break;
            case 3: p1 = Y1p + 64;  break;
            case 4: p1 = Y2p;       p2 = Xn;      break;
            default: p1 = Y2p + 64; p2 = Xn + 64; break;
        }
#pragma unroll
        for (int q = 0; q < 4; q++) {
            int j = ccol + q * 4;
            float4 v = *(const float4*)(p1 + cr * 128 + j);
            if (p2) {
                float4 u = *(const float4*)(p2 + cr * 128 + j);
                v.x = 2.f*v.x - u.x; v.y = 2.f*v.y - u.y;
                v.z = 2.f*v.z - u.z; v.w = 2.f*v.w - u.w;
            }
            xv[q] = v;
        }
    };
    auto storeX = [&](int st, const float4* xv) {
        char* bh = sm + st * GATE_STAGE;
#pragma unroll
        for (int q = 0; q < 4; q++)
            split_store(bh, bh + 9216, cr * 144 + (ccol + q * 4) * 2, xv[q]);
    };

    float acc[8][4];
#pragma unroll
    for (int nt = 0; nt < 8; nt++)
#pragma unroll
        for (int q = 0; q < 4; q++) acc[nt][q] = 0.0f;

    // prologue
    {
        loadW(0, 0);
        float4 xv[4];
        loadX(0, xv);
        storeX(0, xv);
        asm volatile("cp.async.wait_group 0;" ::: "memory");
        __syncthreads();
    }

    for (int ck = 0; ck < 6; ck++) {
        int cur = ck & 1, nxt = cur ^ 1;
        float4 xv[4];
        if (ck < 5) {
            loadW(nxt, ck + 1);
            loadX(ck + 1, xv);
        }

        uint32_t sbase = sb + cur * GATE_STAGE;
#pragma unroll
        for (int ks = 0; ks < 4; ks++) {
            uint32_t ahi[4], alo[4];
            uint32_t aad = (uint32_t)((wm + (g&1)*8 + lr8) * 144
                                      + (ks*16 + (g>>1)*8) * 2);
            ldsm_x4(ahi, sbase + aad);
            ldsm_x4(alo, sbase + 9216 + aad);
#pragma unroll
            for (int np = 0; np < 4; np++) {
                uint32_t bad = (uint32_t)((ks*16 + (g&1)*8 + lr8) * 272
                                          + (wn + np*16 + (g>>1)*8) * 2);
                uint32_t th[4], tl[4];
                ldsm_x4_t(th, sbase + 18432 + bad);
                ldsm_x4_t(tl, sbase + 35840 + bad);
                uint32_t b0h[2] = {th[0], th[1]}, b1h[2] = {th[2], th[3]};
                uint32_t b0l[2] = {tl[0], tl[1]}, b1l[2] = {tl[2], tl[3]};
                mma16816(acc[2*np],   ahi, b0h);
                mma16816(acc[2*np],   ahi, b0l);
                mma16816(acc[2*np],   alo, b0h);
                mma16816(acc[2*np+1], ahi, b1h);
                mma16816(acc[2*np+1], ahi, b1l);
                mma16816(acc[2*np+1], alo, b1h);
            }
        }

        if (ck < 5) {
            storeX(nxt, xv);
            asm volatile("cp.async.wait_group 0;" ::: "memory");
        }
        __syncthreads();
    }

    float* X2sn = X2s + (size_t)n * (BB*HH);
    float* Rn   = R   + (size_t)n * (BB*HH);
    int erow = lane >> 2, ecol = (lane & 3) * 2;
    bool isz = ((wid & 1) == 0);
#pragma unroll
    for (int nt = 0; nt < 8; nt++) {
        int c = wn + nt*8 + ecol;
        float b0 = bias[c], b1 = bias[c+1];
#pragma unroll
        for (int h = 0; h < 2; h++) {
            int b = wm + erow + h*8;
            float s0 = 1.0f / (1.0f + __expf(-(acc[nt][h*2+0] + b0)));
            float s1 = 1.0f / (1.0f + __expf(-(acc[nt][h*2+1] + b1)));
            if (isz) {
                float2 st = *(const float2*)(Xn + b*128 + 64 + c);
                *(float2*)(X2sn + b*64 + c) = make_float2(s0*st.x, s1*st.y);
            } else {
                *(float2*)(Rn + b*64 + (c - 64)) = make_float2(s0, s1);
            }
        }
    }
}

// ---------------------------------------------------------------------------
// Per-node UPDATE via mma.sync bf16x3, double-buffered pipeline + GRU combine.
// smem stages of 36864B: XH +0, XL +9216, WH +18432 (64x144), WL +27648.
#define UPD_STAGE 36864
#define UPD_SMEM  (2*UPD_STAGE + 256)
__global__ __launch_bounds__(256)
void pernode_upd_mma(const float* __restrict__ X,  const float* __restrict__ Y,
                     const float* __restrict__ X2s, const float* __restrict__ Ys,
                     const __nv_bfloat16* __restrict__ Wh,
                     const __nv_bfloat16* __restrict__ Wl,
                     const float* __restrict__ E, const float* __restrict__ bpool,
                     const float* __restrict__ R, float* __restrict__ out) {
    extern __shared__ char sm[];
    uint32_t sb = smem_to_u32(sm);
    float* bias = (float*)(sm + 2*UPD_STAGE);
    int n = blockIdx.x;
    int tid = threadIdx.x, lane = tid & 31, wid = tid >> 5;

    if (tid < 64) {
        float a = 0.0f;
#pragma unroll
        for (int e = 0; e < 16; e++) a += E[n*ED + e] * bpool[e*64 + tid];
        bias[tid] = a;
    }

    const float* Xn   = X   + (size_t)n * BCDIM;
    const float* Y1p  = Y   + (size_t)n * BCDIM;
    const float* Y2p  = Y   + (size_t)(NN + n) * BCDIM;
    const float* X2sn = X2s + (size_t)n * (BB*HH);
    const float* Ys1n = Ys  + (size_t)n * (BB*HH);
    const float* Ys2n = Ys  + (size_t)(NN + n) * (BB*HH);
    const __nv_bfloat16* gWh = Wh + (size_t)n * (3*CC*HH);
    const __nv_bfloat16* gWl = Wl + (size_t)n * (3*CC*HH);

    int wm = (wid >> 1) * 16, wn = (wid & 1) * 32;
    int g = lane >> 3, lr8 = lane & 7;
    int cr = tid >> 2;
    int ccol = (tid & 3) * 16;

    auto loadW = [&](int st, int ck) {
        int kc0 = ck * 64;
        uint32_t base = sb + st * UPD_STAGE;
#pragma unroll
        for (int q = 0; q < 2; q++) {
            int m = tid + q * 256;
            int kr = m >> 3, o8 = m & 7;
            uint32_t so = (uint32_t)(kr * 144 + o8 * 16);
            size_t eoff = (size_t)(kc0 + kr) * 64 + o8 * 8;
            cp_async16(base + 18432 + so, gWh + eoff);
            cp_async16(base + 27648 + so, gWl + eoff);
        }
        CP_COMMIT();
    };
    auto loadX = [&](int ck, float4* xv) {
        const float* p1;
        const float* p2 = nullptr;
        int str;
        switch (ck) {
            case 0: p1 = Xn;   str = 128; break;
            case 1: p1 = X2sn; str = 64;  break;
            case 2: p1 = Y1p;  str = 128; break;
            case 3: p1 = Ys1n; str = 64;  break;
            case 4: p1 = Y2p;  p2 = Xn;   str = 128; break;
            default: p1 = Ys2n; p2 = X2sn; str = 64; break;
        }
#pragma unroll
        for (int q = 0; q < 4; q++) {
            int j = ccol + q * 4;
            float4 v = *(const float4*)(p1 + cr * str + j);
            if (p2) {
                float4 u = *(const float4*)(p2 + cr * str + j);
                v.x = 2.f*v.x - u.x; v.y = 2.f*v.y - u.y;
                v.z = 2.f*v.z - u.z; v.w = 2.f*v.w - u.w;
            }
            xv[q] = v;
        }
    };
    auto storeX = [&](int st, const float4* xv) {
        char* bh = sm + st * UPD_STAGE;
#pragma unroll
        for (int q = 0; q < 4; q++)
            split_store(bh, bh + 9216, cr * 144 + (ccol + q * 4) * 2, xv[q]);
    };

    float acc[4][4];
#pragma unroll
    for (int nt = 0; nt < 4; nt++)
#pragma unroll
        for (int q = 0; q < 4; q++) acc[nt][q] = 0.0f;

    {
        loadW(0, 0);
        float4 xv[4];
        loadX(0, xv);
        storeX(0, xv);
        asm volatile("cp.async.wait_group 0;" ::: "memory");
        __syncthreads();
    }

    for (int ck = 0; ck < 6; ck++) {
        int cur = ck & 1, nxt = cur ^ 1;
        float4 xv[4];
        if (ck < 5) {
            loadW(nxt, ck + 1);
            loadX(ck + 1, xv);
        }

        uint32_t sbase = sb + cur * UPD_STAGE;
#pragma unroll
        for (int ks = 0; ks < 4; ks++) {
            uint32_t ahi[4], alo[4];
            uint32_t aad = (uint32_t)((wm + (g&1)*8 + lr8) * 144
                                      + (ks*16 + (g>>1)*8) * 2);
            ldsm_x4(ahi, sbase + aad);
            ldsm_x4(alo, sbase + 9216 + aad);
#pragma unroll
            for (int np = 0; np < 2; np++) {
                uint32_t bad = (uint32_t)((ks*16 + (g&1)*8 + lr8) * 144
                                          + (wn + np*16 + (g>>1)*8) * 2);
                uint32_t th[4], tl[4];
                ldsm_x4_t(th, sbase + 18432 + bad);
                ldsm_x4_t(tl, sbase + 27648 + bad);
                uint32_t b0h[2] = {th[0], th[1]}, b1h[2] = {th[2], th[3]};
                uint32_t b0l[2] = {tl[0], tl[1]}, b1l[2] = {tl[2], tl[3]};
                mma16816(acc[2*np],   ahi, b0h);
                mma16816(acc[2*np],   ahi, b0l);
                mma16816(acc[2*np],   alo, b0h);
                mma16816(acc[2*np+1], ahi, b1h);
                mma16816(acc[2*np+1], ahi, b1l);
                mma16816(acc[2*np+1], alo, b1h);
            }
        }

        if (ck < 5) {
            storeX(nxt, xv);
            asm volatile("cp.async.wait_group 0;" ::: "memory");
        }
        __syncthreads();
    }

    const float* Rn = R + (size_t)n * (BB*HH);
    int erow = lane >> 2, ecol = (lane & 3) * 2;
#pragma unroll
    for (int nt = 0; nt < 4; nt++) {
        int c = wn + nt*8 + ecol;
        float b0 = bias[c], b1 = bias[c+1];
#pragma unroll
        for (int h = 0; h < 2; h++) {
            int b = wm + erow + h*8;
            float hc0 = tanhf(acc[nt][h*2+0] + b0);
            float hc1 = tanhf(acc[nt][h*2+1] + b1);
            float2 r  = *(const float2*)(Rn + b*64 + c);
            float2 st = *(const float2*)(Xn + b*128 + 64 + c);
            float o0 = r.x * st.x + (1.0f - r.x) * hc0;
            float o1 = r.y * st.y + (1.0f - r.y) * hc1;
            *(float2*)(out + (size_t)b * (NN*HH) + n*HH + c) = make_float2(o0, o1);
        }
    }
}

// ---------------------------------------------------------------------------
extern "C" void kernel_launch(void* const* d_in, const int* in_sizes, int n_in,
                              void* d_out, int out_size) {
    const float* x     = (const float*)d_in[0];
    const float* state = (const float*)d_in[1];
    const float* E     = (const float*)d_in[2];
    const float* gWp   = (const float*)d_in[3];
    const float* gbp   = (const float*)d_in[4];
    const float* uWp   = (const float*)d_in[5];
    const float* ubp   = (const float*)d_in[6];
    float* out = (float*)d_out;

    float *X, *X2s, *Y, *Ys, *R;
    __nv_bfloat16 *Ah, *Al, *Ath, *Atl, *Bt1, *Bt2, *Wh, *Wl, *Whu, *Wlu;
    cudaGetSymbolAddress((void**)&X,   g_X);
    cudaGetSymbolAddress((void**)&X2s, g_X2s);
    cudaGetSymbolAddress((void**)&Y,   g_Y);
    cudaGetSymbolAddress((void**)&Ys,  g_Ys);
    cudaGetSymbolAddress((void**)&R,   g_R);
    cudaGetSymbolAddress((void**)&Ah,  g_Ah);
    cudaGetSymbolAddress((void**)&Al,  g_Al);
    cudaGetSymbolAddress((void**)&Ath, g_Ath);
    cudaGetSymbolAddress((void**)&Atl, g_Atl);
    cudaGetSymbolAddress((void**)&Bt1, g_Bt1);
    cudaGetSymbolAddress((void**)&Bt2, g_Bt2);
    cudaGetSymbolAddress((void**)&Wh,  g_Wh);
    cudaGetSymbolAddress((void**)&Wl,  g_Wl);
    cudaGetSymbolAddress((void**)&Whu, g_Whu);
    cudaGetSymbolAddress((void**)&Wlu, g_Wlu);

    cudaFuncSetAttribute(mma_gemm_kernel,
                         cudaFuncAttributeMaxDynamicSharedMemorySize, GEMM_SMEM);
    cudaFuncSetAttribute(pernode_gate_mma,
                         cudaFuncAttributeMaxDynamicSharedMemorySize, GATE_SMEM);
    cudaFuncSetAttribute(pernode_upd_mma,
                         cudaFuncAttributeMaxDynamicSharedMemorySize, UPD_SMEM);

    // fork side branches off the capture-origin stream
    cudaEventRecord(g_fork.fork, 0);
    cudaStreamWaitEvent(g_fork.s1, g_fork.fork, 0);
    cudaStreamWaitEvent(g_fork.s2, g_fork.fork, 0);

    // --- branch s1: adjacency (eA0), then A^2 with split epilogue (eA)
    compute_A_kernel<<<NN, 256, 0, g_fork.s1>>>(E, Ah, Al, Ath, Atl);
    cudaEventRecord(g_fork.eA0, g_fork.s1);
    mma_gemm_kernel<<<dim3(NN/128, NN/128), 256, GEMM_SMEM, g_fork.s1>>>(
        Ah, Al, Ath, Atl, nullptr, Ah + (size_t)NN*NN, Al + (size_t)NN*NN, NN, NN, NN);
    cudaEventRecord(g_fork.eA, g_fork.s1);

    // --- branch s2: per-node weight pools
    build_W_kernel<<<dim3(48, 64), 256, 0, g_fork.s2>>>(gWp, E, Wh, Wl, 3*CC*CC);
    cudaEventRecord(g_fork.eWg, g_fork.s2);
    build_W_kernel<<<dim3(24, 64), 256, 0, g_fork.s2>>>(uWp, E, Whu, Wlu, 3*CC*HH);
    cudaEventRecord(g_fork.eWu, g_fork.s2);

    // --- main branch (stream 0)
    build_X_fused_kernel<<<dim3(BCDIM/32, NN/32), dim3(32, 8)>>>(x, state, X, Bt1, Bt2);

    // GEMM1 A-half: Y[0:1024) = A @ X^T — needs only A (eA0) + Bt
    cudaStreamWaitEvent(0, g_fork.eA0, 0);
    mma_gemm_kernel<<<dim3(BCDIM/128, NN/128), 256, GEMM_SMEM>>>(
        Ah, Al, Bt1, Bt2, Y, nullptr, nullptr, NN, BCDIM, NN);
    // GEMM1 A^2-half: Y[1024:2048) — needs A^2 (eA)
    cudaStreamWaitEvent(0, g_fork.eA, 0);
    mma_gemm_kernel<<<dim3(BCDIM/128, NN/128), 256, GEMM_SMEM>>>(
        Ah + (size_t)NN*NN, Al + (size_t)NN*NN, Bt1, Bt2,
        Y + (size_t)NN*BCDIM, nullptr, nullptr, NN, BCDIM, NN);

    cudaStreamWaitEvent(0, g_fork.eWg, 0);
    pernode_gate_mma<<<NN, 256, GATE_SMEM>>>(X, Y, Wh, Wl, E, gbp, X2s, R);

    transpose_split_kernel<<<dim3(BB*HH/32, NN/32), dim3(32, 8)>>>(X2s, Bt1, Bt2, BB*HH);
    mma_gemm_kernel<<<dim3(BB*HH/128, NN/128), 256, GEMM_SMEM>>>(
        Ah, Al, Bt1, Bt2, Ys, nullptr, nullptr, NN, BB*HH, NN);
    mma_gemm_kernel<<<dim3(BB*HH/128, NN/128), 256, GEMM_SMEM>>>(
        Ah + (size_t)NN*NN, Al + (size_t)NN*NN, Bt1, Bt2,
        Ys + (size_t)NN*BB*HH, nullptr, nullptr, NN, BB*HH, NN);

    cudaStreamWaitEvent(0, g_fork.eWu, 0);
    pernode_upd_mma<<<NN, 256, UPD_SMEM>>>(X, Y, X2s, Ys, Whu, Wlu, E, ubp, R, out);
}

// round 10
// speedup vs baseline: 1.0919x; 1.0919x over previous
#include <cuda_runtime.h>
#include <cuda_bf16.h>
#include <cstdint>

#define NN 1024
#define BB 64
#define CC 128
#define HH 64
#define ED 16
#define BCDIM (BB*CC)   /* 8192 */
#define SHDIM (BB*HH)   /* 4096 */

// ---------------------------------------------------------------------------
// Device-global scratch
__device__ float g_X  [NN*BCDIM];                  // fp32 concat(x,state) [n, b*128+c]
__device__ float g_X2s[NN*SHDIM];                  // fp32 z*state compact [n, b*64+c]
__device__ float g_R  [NN*SHDIM];                  // r gate
__device__ __nv_bfloat16 g_Xh [NN*BCDIM];          // X hi/lo, [n, bc]
__device__ __nv_bfloat16 g_Xl [NN*BCDIM];
__device__ __nv_bfloat16 g_Yh [(size_t)2*NN*BCDIM]; // rows [0,NN): A@X ; [NN,2NN): 2*A^2@X - X
__device__ __nv_bfloat16 g_Yl [(size_t)2*NN*BCDIM];
__device__ __nv_bfloat16 g_X2sh[NN*SHDIM];
__device__ __nv_bfloat16 g_X2sl[NN*SHDIM];
__device__ __nv_bfloat16 g_Ysh[(size_t)2*NN*SHDIM]; // rows [0,NN): A@X2s ; [NN,2NN): combined
__device__ __nv_bfloat16 g_Ysl[(size_t)2*NN*SHDIM];
__device__ __nv_bfloat16 g_Ah [2*NN*NN];           // rows [0,NN): A hi; [NN,2NN): A^2 hi
__device__ __nv_bfloat16 g_Al [2*NN*NN];
__device__ __nv_bfloat16 g_Ath[NN*NN];
__device__ __nv_bfloat16 g_Atl[NN*NN];
__device__ __nv_bfloat16 g_Bt1[(size_t)BCDIM*NN];
__device__ __nv_bfloat16 g_Bt2[(size_t)BCDIM*NN];
__device__ __nv_bfloat16 g_Wh [(size_t)NN*3*CC*CC];
__device__ __nv_bfloat16 g_Wl [(size_t)NN*3*CC*CC];
__device__ __nv_bfloat16 g_Whu[(size_t)NN*3*CC*HH];
__device__ __nv_bfloat16 g_Wlu[(size_t)NN*3*CC*HH];

// ---------------------------------------------------------------------------
// Streams/events for graph-fork
struct ForkCtx {
    cudaStream_t s1, s2;
    cudaEvent_t fork, eA, eWg, eWu;
    ForkCtx() {
        cudaStreamCreateWithFlags(&s1, cudaStreamNonBlocking);
        cudaStreamCreateWithFlags(&s2, cudaStreamNonBlocking);
        cudaEventCreateWithFlags(&fork, cudaEventDisableTiming);
        cudaEventCreateWithFlags(&eA,   cudaEventDisableTiming);
        cudaEventCreateWithFlags(&eWg,  cudaEventDisableTiming);
        cudaEventCreateWithFlags(&eWu,  cudaEventDisableTiming);
    }
};
static ForkCtx g_fork;

// ---------------------------------------------------------------------------
// PTX helpers (sm_80-baseline only)
__device__ __forceinline__ uint32_t smem_to_u32(const void* p) {
    uint32_t a;
    asm("{ .reg .u64 t; cvta.to.shared.u64 t, %1; cvt.u32.u64 %0, t; }"
        : "=r"(a) : "l"(p));
    return a;
}
__device__ __forceinline__ void cp_async16(uint32_t dst, const void* src) {
    asm volatile("cp.async.cg.shared.global [%0], [%1], 16;" :: "r"(dst), "l"(src));
}
#define CP_COMMIT() asm volatile("cp.async.commit_group;" ::: "memory")
#define CP_WAIT0()  asm volatile("cp.async.wait_group 0;" ::: "memory")

__device__ __forceinline__ void ldsm_x4(uint32_t* r, uint32_t addr) {
    asm volatile("ldmatrix.sync.aligned.m8n8.x4.shared.b16 {%0,%1,%2,%3}, [%4];"
        : "=r"(r[0]), "=r"(r[1]), "=r"(r[2]), "=r"(r[3]) : "r"(addr));
}
__device__ __forceinline__ void ldsm_x4_t(uint32_t* r, uint32_t addr) {
    asm volatile("ldmatrix.sync.aligned.m8n8.x4.trans.shared.b16 {%0,%1,%2,%3}, [%4];"
        : "=r"(r[0]), "=r"(r[1]), "=r"(r[2]), "=r"(r[3]) : "r"(addr));
}
__device__ __forceinline__ void mma16816(float* d, const uint32_t* a, const uint32_t* b) {
    asm volatile(
        "mma.sync.aligned.m16n8k16.row.col.f32.bf16.bf16.f32 "
        "{%0,%1,%2,%3}, {%4,%5,%6,%7}, {%8,%9}, {%0,%1,%2,%3};"
        : "+f"(d[0]), "+f"(d[1]), "+f"(d[2]), "+f"(d[3])
        : "r"(a[0]), "r"(a[1]), "r"(a[2]), "r"(a[3]), "r"(b[0]), "r"(b[1]));
}
__device__ __forceinline__ uint32_t pack_split2(float a, float b, uint32_t* lo) {
    __nv_bfloat16 h0 = __float2bfloat16(a);
    __nv_bfloat16 h1 = __float2bfloat16(b);
    __nv_bfloat16 l0 = __float2bfloat16(a - __bfloat162float(h0));
    __nv_bfloat16 l1 = __float2bfloat16(b - __bfloat162float(h1));
    uint32_t hi;
    ((__nv_bfloat16*)&hi)[0] = h0; ((__nv_bfloat16*)&hi)[1] = h1;
    ((__nv_bfloat16*)lo)[0] = l0;  ((__nv_bfloat16*)lo)[1] = l1;
    return hi;
}

// ---------------------------------------------------------------------------
// build X fp32 + Xh/Xl [n,bc] + transposed Bt1/Bt2 [bc,n]
__global__ void build_X_fused_kernel(const float* __restrict__ x,
                                     const float* __restrict__ st,
                                     float* __restrict__ X,
                                     __nv_bfloat16* __restrict__ Xh,
                                     __nv_bfloat16* __restrict__ Xl,
                                     __nv_bfloat16* __restrict__ hi,
                                     __nv_bfloat16* __restrict__ lo) {
    __shared__ float t[32][33];
    int bc0 = blockIdx.x * 32;
    int n0  = blockIdx.y * 32;
    int tx = threadIdx.x, ty = threadIdx.y;
#pragma unroll
    for (int i = 0; i < 4; i++) {
        int n = n0 + ty + 8*i;
        int bc = bc0 + tx;
        int c = bc & 127, b = bc >> 7;
        float v = (c < HH) ? x [(size_t)b * (NN*HH) + n*HH + c]
                           : st[(size_t)b * (NN*HH) + n*HH + (c - HH)];
        size_t o = (size_t)n * BCDIM + bc;
        X[o] = v;
        __nv_bfloat16 h = __float2bfloat16(v);
        Xh[o] = h;
        Xl[o] = __float2bfloat16(v - __bfloat162float(h));
        t[ty + 8*i][tx] = v;
    }
    __syncthreads();
#pragma unroll
    for (int i = 0; i < 4; i++) {
        float v = t[tx][ty + 8*i];
        __nv_bfloat16 h = __float2bfloat16(v);
        size_t o = (size_t)(bc0 + ty + 8*i) * NN + n0 + tx;
        hi[o] = h;
        lo[o] = __float2bfloat16(v - __bfloat162float(h));
    }
}

// ---------------------------------------------------------------------------
__global__ void compute_A_kernel(const float* __restrict__ E,
                                 __nv_bfloat16* __restrict__ Ah,
                                 __nv_bfloat16* __restrict__ Al,
                                 __nv_bfloat16* __restrict__ Ath,
                                 __nv_bfloat16* __restrict__ Atl) {
    int i = blockIdx.x;
    int tid = threadIdx.x;
    __shared__ float Ei[ED];
    __shared__ float red[256];
    if (tid < ED) Ei[tid] = E[i*ED + tid];
    __syncthreads();

    float v[4];
    float vmax = 0.0f;
#pragma unroll
    for (int p = 0; p < 4; p++) {
        int j = tid + p * 256;
        const float4* Ej = (const float4*)(E + (size_t)j * ED);
        float4 e0 = Ej[0], e1 = Ej[1], e2 = Ej[2], e3 = Ej[3];
        float d = Ei[0]*e0.x + Ei[1]*e0.y + Ei[2]*e0.z + Ei[3]*e0.w
                + Ei[4]*e1.x + Ei[5]*e1.y + Ei[6]*e1.z + Ei[7]*e1.w
                + Ei[8]*e2.x + Ei[9]*e2.y + Ei[10]*e2.z + Ei[11]*e2.w
                + Ei[12]*e3.x + Ei[13]*e3.y + Ei[14]*e3.z + Ei[15]*e3.w;
        d = fmaxf(d, 0.0f);
        v[p] = d;
        vmax = fmaxf(vmax, d);
    }
    red[tid] = vmax; __syncthreads();
    for (int s = 128; s > 0; s >>= 1) {
        if (tid < s) red[tid] = fmaxf(red[tid], red[tid + s]);
        __syncthreads();
    }
    vmax = red[0];
    __syncthreads();
    float lsum = 0.0f;
#pragma unroll
    for (int p = 0; p < 4; p++) { v[p] = __expf(v[p] - vmax); lsum += v[p]; }
    red[tid] = lsum; __syncthreads();
    for (int s = 128; s > 0; s >>= 1) {
        if (tid < s) red[tid] += red[tid + s];
        __syncthreads();
    }
    float inv = 1.0f / red[0];
#pragma unroll
    for (int p = 0; p < 4; p++) {
        int j = tid + p * 256;
        float a = v[p] * inv;
        __nv_bfloat16 h = __float2bfloat16(a);
        __nv_bfloat16 l = __float2bfloat16(a - __bfloat162float(h));
        Ah [(size_t)i * NN + j] = h;
        Al [(size_t)i * NN + j] = l;
        Ath[(size_t)j * NN + i] = h;
        Atl[(size_t)j * NN + i] = l;
    }
}

// ---------------------------------------------------------------------------
// transpose + split: src fp32 [NN, W] -> hi/lo bf16 [W, NN]
__global__ void transpose_split_kernel(const float* __restrict__ src,
                                       __nv_bfloat16* __restrict__ hi,
                                       __nv_bfloat16* __restrict__ lo, int W) {
    __shared__ float t[32][33];
    int m0 = blockIdx.x * 32;
    int n0 = blockIdx.y * 32;
    int tx = threadIdx.x, ty = threadIdx.y;
#pragma unroll
    for (int i = 0; i < 4; i++)
        t[ty + 8*i][tx] = src[(size_t)(n0 + ty + 8*i) * W + m0 + tx];
    __syncthreads();
#pragma unroll
    for (int i = 0; i < 4; i++) {
        float v = t[tx][ty + 8*i];
        __nv_bfloat16 h = __float2bfloat16(v);
        size_t o = (size_t)(m0 + ty + 8*i) * NN + n0 + tx;
        hi[o] = h;
        lo[o] = __float2bfloat16(v - __bfloat162float(h));
    }
}

// ---------------------------------------------------------------------------
// Big bf16x3 GEMM: acc = (Ahi+Alo) @ (Bhi+Blo)^T.
// Epilogue: if block_row >= comb_start, acc = 2*acc - Xref[row-comb_start];
// always written as bf16 hi/lo split to Ch/Cl.
#define GSTRIDE 144
#define HALF_BYTES (128*GSTRIDE)
#define STAGE_BYTES (4*HALF_BYTES)
#define GEMM_SMEM (2*STAGE_BYTES)

__global__ __launch_bounds__(256, 1)
void mma_gemm_kernel(const __nv_bfloat16* __restrict__ Ahi,
                     const __nv_bfloat16* __restrict__ Alo,
                     const __nv_bfloat16* __restrict__ Bhi,
                     const __nv_bfloat16* __restrict__ Blo,
                     __nv_bfloat16* __restrict__ Ch,
                     __nv_bfloat16* __restrict__ Cl,
                     const float* __restrict__ Xref, int comb_start,
                     int M, int N, int K) {
    extern __shared__ char smem[];
    uint32_t sb = smem_to_u32(smem);
    int tid = threadIdx.x;
    int lane = tid & 31, wid = tid >> 5;
    int wm = (wid >> 1) * 32;
    int wn = (wid & 1) * 64;
    int block_row = blockIdx.y * 128;
    int block_col = blockIdx.x * 128;

    const char* gA0 = (const char*)(Ahi + (size_t)block_row * K);
    const char* gA1 = (const char*)(Alo + (size_t)block_row * K);
    const char* gB0 = (const char*)(Bhi + (size_t)block_col * K);
    const char* gB1 = (const char*)(Blo + (size_t)block_col * K);

    int lr_ = tid >> 3;
    int lc_ = (tid & 7) * 16;

    float acc[2][8][4];
#pragma unroll
    for (int mt = 0; mt < 2; mt++)
#pragma unroll
        for (int nt = 0; nt < 8; nt++)
#pragma unroll
            for (int q = 0; q < 4; q++) acc[mt][nt][q] = 0.0f;

    int g = lane >> 3;
    int lr8 = lane & 7;
    int a_row = wm + (g & 1) * 8 + lr8;
    int a_kc  = (g >> 1) * 8;
    int b_row = wn + (g >> 1) * 8 + lr8;
    int b_kc  = (g & 1) * 8;

    int nstages = K >> 6;

    auto load_stage = [&](int st, int kt) {
        uint32_t base = sb + st * STAGE_BYTES;
        size_t k0b = (size_t)(kt * 64) * 2;
#pragma unroll
        for (int q = 0; q < 4; q++) {
            int r = lr_ + q * 32;
            uint32_t so = (uint32_t)(r * GSTRIDE + lc_);
            size_t go = (size_t)r * (K * 2) + k0b + lc_;
            cp_async16(base + 0*HALF_BYTES + so, gA0 + go);
            cp_async16(base + 1*HALF_BYTES + so, gA1 + go);
            cp_async16(base + 2*HALF_BYTES + so, gB0 + go);
            cp_async16(base + 3*HALF_BYTES + so, gB1 + go);
        }
        CP_COMMIT();
    };

    load_stage(0, 0);

    for (int kt = 0; kt < nstages; kt++) {
        int st = kt & 1;
        if (kt + 1 < nstages) {
            load_stage(st ^ 1, kt + 1);
            asm volatile("cp.async.wait_group 1;" ::: "memory");
        } else {
            CP_WAIT0();
        }
        __syncthreads();

        uint32_t aHiB = sb + st * STAGE_BYTES;
        uint32_t aLoB = aHiB + HALF_BYTES;
        uint32_t bHiB = aLoB + HALF_BYTES;
        uint32_t bLoB = bHiB + HALF_BYTES;

#pragma unroll
        for (int ks = 0; ks < 4; ks++) {
            int kc = ks * 16;
            uint32_t ahi[2][4], alo[2][4];
#pragma unroll
            for (int mt = 0; mt < 2; mt++) {
                uint32_t ad = (uint32_t)((a_row + mt*16) * GSTRIDE + (kc + a_kc) * 2);
                ldsm_x4(ahi[mt], aHiB + ad);
                ldsm_x4(alo[mt], aLoB + ad);
            }
            uint32_t bhi[8][2], blo[8][2];
#pragma unroll
            for (int np = 0; np < 4; np++) {
                uint32_t bd = (uint32_t)((b_row + np*16) * GSTRIDE + (kc + b_kc) * 2);
                uint32_t t[4];
                ldsm_x4(t, bHiB + bd);
                bhi[2*np][0] = t[0]; bhi[2*np][1] = t[1];
                bhi[2*np+1][0] = t[2]; bhi[2*np+1][1] = t[3];
                ldsm_x4(t, bLoB + bd);
                blo[2*np][0] = t[0]; blo[2*np][1] = t[1];
                blo[2*np+1][0] = t[2]; blo[2*np+1][1] = t[3];
            }
#pragma unroll
            for (int mt = 0; mt < 2; mt++)
#pragma unroll
                for (int nt = 0; nt < 8; nt++) {
                    mma16816(acc[mt][nt], ahi[mt], bhi[nt]);
                    mma16816(acc[mt][nt], ahi[mt], blo[nt]);
                    mma16816(acc[mt][nt], alo[mt], bhi[nt]);
                }
        }
        __syncthreads();
    }

    int erow = lane >> 2, ecol = (lane & 3) * 2;
    bool comb = (block_row >= comb_start);
#pragma unroll
    for (int mt = 0; mt < 2; mt++) {
#pragma unroll
        for (int nt = 0; nt < 8; nt++) {
            size_t cc = (size_t)block_col + wn + nt*8 + ecol;
#pragma unroll
            for (int h = 0; h < 2; h++) {
                size_t row = (size_t)block_row + wm + mt*16 + erow + h*8;
                float v0 = acc[mt][nt][h*2+0];
                float v1 = acc[mt][nt][h*2+1];
                if (comb) {
                    const float* xr = Xref + (row - comb_start) * N + cc;
                    v0 = 2.0f*v0 - xr[0];
                    v1 = 2.0f*v1 - xr[1];
                }
                uint32_t lo;
                uint32_t hi = pack_split2(v0, v1, &lo);
                *(uint32_t*)(Ch + row * N + cc) = hi;
                *(uint32_t*)(Cl + row * N + cc) = lo;
            }
        }
    }
}

// ---------------------------------------------------------------------------
// W[n,:] = sum_e E[n,e] * Wp[e,:], output bf16 hi/lo (4-node groups: low regs)
__global__ __launch_bounds__(256)
void build_W_kernel(const float* __restrict__ Wp,
                    const float* __restrict__ E,
                    __nv_bfloat16* __restrict__ Wh,
                    __nv_bfloat16* __restrict__ Wl, int TC) {
    int ng = blockIdx.y;
    int cbase = blockIdx.x * 1024;
    __shared__ float Es[16][16];
    {
        int nn = threadIdx.x >> 4, e = threadIdx.x & 15;
        if (threadIdx.x < 256) Es[nn][e] = E[(ng * 16 + nn) * ED + e];
    }
    __syncthreads();
#pragma unroll 1
    for (int cc = 0; cc < 1024; cc += 256) {
        int c = cbase + cc + threadIdx.x;
        float wp[16];
#pragma unroll
        for (int e = 0; e < 16; e++) wp[e] = Wp[(size_t)e * TC + c];
#pragma unroll 1
        for (int nn0 = 0; nn0 < 16; nn0 += 4) {
#pragma unroll
            for (int k = 0; k < 4; k++) {
                int nn = nn0 + k;
                float a = 0.0f;
#pragma unroll
                for (int e = 0; e < 16; e++) a += Es[nn][e] * wp[e];
                __nv_bfloat16 h = __float2bfloat16(a);
                size_t o = (size_t)(ng * 16 + nn) * TC + c;
                Wh[o] = h;
                Wl[o] = __float2bfloat16(a - __bfloat162float(h));
            }
        }
    }
}

// ---------------------------------------------------------------------------
// Per-node GATE: pure cp.async -> ldsm -> mma (all operands pre-split bf16).
// smem: XH +0 (64x144B), XL +9216, WH +18432 (64x272B), WL +35840, bias +53248.
#define GATE_SMEM 53760
__global__ __launch_bounds__(256)
void pernode_gate_mma(const float* __restrict__ X,
                      const __nv_bfloat16* __restrict__ Xh,
                      const __nv_bfloat16* __restrict__ Xl,
                      const __nv_bfloat16* __restrict__ Yh,
                      const __nv_bfloat16* __restrict__ Yl,
                      const __nv_bfloat16* __restrict__ Wh,
                      const __nv_bfloat16* __restrict__ Wl,
                      const float* __restrict__ E, const float* __restrict__ bpool,
                      float* __restrict__ X2s,
                      __nv_bfloat16* __restrict__ X2sh,
                      __nv_bfloat16* __restrict__ X2sl,
                      float* __restrict__ R) {
    extern __shared__ char sm[];
    uint32_t sb = smem_to_u32(sm);
    float* bias = (float*)(sm + 53248);
    int n = blockIdx.x;
    int tid = threadIdx.x, lane = tid & 31, wid = tid >> 5;

    if (tid < 128) {
        float a = 0.0f;
#pragma unroll
        for (int e = 0; e < 16; e++) a += E[n*ED + e] * bpool[e*128 + tid];
        bias[tid] = a;
    }

    const float* Xn = X + (size_t)n * BCDIM;
    const __nv_bfloat16* gWh = Wh + (size_t)n * (3*CC*CC);
    const __nv_bfloat16* gWl = Wl + (size_t)n * (3*CC*CC);

    // chunk source table: {hi ptr, lo ptr} with column offset; row stride 128
    const __nv_bfloat16* srcH[6];
    const __nv_bfloat16* srcL[6];
    {
        const __nv_bfloat16* xh = Xh + (size_t)n * BCDIM;
        const __nv_bfloat16* xl = Xl + (size_t)n * BCDIM;
        const __nv_bfloat16* y1h = Yh + (size_t)n * BCDIM;
        const __nv_bfloat16* y1l = Yl + (size_t)n * BCDIM;
        const __nv_bfloat16* y2h = Yh + (size_t)(NN + n) * BCDIM;
        const __nv_bfloat16* y2l = Yl + (size_t)(NN + n) * BCDIM;
        srcH[0] = xh;      srcL[0] = xl;
        srcH[1] = xh + 64; srcL[1] = xl + 64;
        srcH[2] = y1h;     srcL[2] = y1l;
        srcH[3] = y1h + 64; srcL[3] = y1l + 64;
        srcH[4] = y2h;     srcL[4] = y2l;
        srcH[5] = y2h + 64; srcL[5] = y2l + 64;
    }

    int wm = (wid >> 1) * 16, wn = (wid & 1) * 64;
    int g = lane >> 3, lr8 = lane & 7;

    float acc[8][4];
#pragma unroll
    for (int nt = 0; nt < 8; nt++)
#pragma unroll
        for (int q = 0; q < 4; q++) acc[nt][q] = 0.0f;

    for (int ck = 0; ck < 6; ck++) {
        // W chunk: 64k x 128o, both halves
        {
            int kc0 = ck * 64;
#pragma unroll
            for (int q = 0; q < 4; q++) {
                int m = tid + q * 256;
                int kr = m >> 4, o8 = m & 15;
                uint32_t so = (uint32_t)(kr * 272 + o8 * 16);
                size_t eoff = (size_t)(kc0 + kr) * 128 + o8 * 8;
                cp_async16(sb + 18432 + so, gWh + eoff);
                cp_async16(sb + 35840 + so, gWl + eoff);
            }
        }
        // A chunk: 64b x 64k, both halves
        {
            const __nv_bfloat16* ph = srcH[ck];
            const __nv_bfloat16* pl = srcL[ck];
#pragma unroll
            for (int q = 0; q < 2; q++) {
                int m = tid + q * 256;
                int r = m >> 3, c8 = m & 7;
                uint32_t so = (uint32_t)(r * 144 + c8 * 16);
                size_t eoff = (size_t)r * 128 + c8 * 8;
                cp_async16(sb + so, ph + eoff);
                cp_async16(sb + 9216 + so, pl + eoff);
            }
        }
        CP_COMMIT();
        CP_WAIT0();
        __syncthreads();

#pragma unroll
        for (int ks = 0; ks < 4; ks++) {
            uint32_t ahi[4], alo[4];
            uint32_t aad = (uint32_t)((wm + (g&1)*8 + lr8) * 144
                                      + (ks*16 + (g>>1)*8) * 2);
            ldsm_x4(ahi, sb + aad);
            ldsm_x4(alo, sb + 9216 + aad);
#pragma unroll
            for (int np = 0; np < 4; np++) {
                uint32_t bad = (uint32_t)((ks*16 + (g&1)*8 + lr8) * 272
                                          + (wn + np*16 + (g>>1)*8) * 2);
                uint32_t th[4], tl[4];
                ldsm_x4_t(th, sb + 18432 + bad);
                ldsm_x4_t(tl, sb + 35840 + bad);
                uint32_t b0h[2] = {th[0], th[1]}, b1h[2] = {th[2], th[3]};
                uint32_t b0l[2] = {tl[0], tl[1]}, b1l[2] = {tl[2], tl[3]};
                mma16816(acc[2*np],   ahi, b0h);
                mma16816(acc[2*np],   ahi, b0l);
                mma16816(acc[2*np],   alo, b0h);
                mma16816(acc[2*np+1], ahi, b1h);
                mma16816(acc[2*np+1], ahi, b1l);
                mma16816(acc[2*np+1], alo, b1h);
            }
        }
        __syncthreads();
    }

    float* X2sn = X2s + (size_t)n * SHDIM;
    __nv_bfloat16* X2shn = X2sh + (size_t)n * SHDIM;
    __nv_bfloat16* X2sln = X2sl + (size_t)n * SHDIM;
    float* Rn = R + (size_t)n * SHDIM;
    int erow = lane >> 2, ecol = (lane & 3) * 2;
    bool isz = ((wid & 1) == 0);
#pragma unroll
    for (int nt = 0; nt < 8; nt++) {
        int c = wn + nt*8 + ecol;
        float b0 = bias[c], b1 = bias[c+1];
#pragma unroll
        for (int h = 0; h < 2; h++) {
            int b = wm + erow + h*8;
            float s0 = 1.0f / (1.0f + __expf(-(acc[nt][h*2+0] + b0)));
            float s1 = 1.0f / (1.0f + __expf(-(acc[nt][h*2+1] + b1)));
            if (isz) {
                float2 st = *(const float2*)(Xn + b*128 + 64 + c);
                float z0 = s0 * st.x, z1 = s1 * st.y;
                *(float2*)(X2sn + b*64 + c) = make_float2(z0, z1);
                uint32_t lo;
                uint32_t hi = pack_split2(z0, z1, &lo);
                *(uint32_t*)(X2shn + b*64 + c) = hi;
                *(uint32_t*)(X2sln + b*64 + c) = lo;
            } else {
                *(float2*)(Rn + b*64 + (c - 64)) = make_float2(s0, s1);
            }
        }
    }
}

// ---------------------------------------------------------------------------
// Per-node UPDATE: pure cp.async -> ldsm -> mma + GRU combine.
// smem: XH +0, XL +9216, WH +18432 (64x144B), WL +27648, bias +36864.
#define UPD_SMEM 37120
__global__ __launch_bounds__(256)
void pernode_upd_mma(const float* __restrict__ X,
                     const __nv_bfloat16* __restrict__ Xh,
                     const __nv_bfloat16* __restrict__ Xl,
                     const __nv_bfloat16* __restrict__ Yh,
                     const __nv_bfloat16* __restrict__ Yl,
                     const __nv_bfloat16* __restrict__ X2sh,
                     const __nv_bfloat16* __restrict__ X2sl,
                     const __nv_bfloat16* __restrict__ Ysh,
                     const __nv_bfloat16* __restrict__ Ysl,
                     const __nv_bfloat16* __restrict__ Wh,
                     const __nv_bfloat16* __restrict__ Wl,
                     const float* __restrict__ E, const float* __restrict__ bpool,
                     const float* __restrict__ R, float* __restrict__ out) {
    extern __shared__ char sm[];
    uint32_t sb = smem_to_u32(sm);
    float* bias = (float*)(sm + 36864);
    int n = blockIdx.x;
    int tid = threadIdx.x, lane = tid & 31, wid = tid >> 5;

    if (tid < 64) {
        float a = 0.0f;
#pragma unroll
        for (int e = 0; e < 16; e++) a += E[n*ED + e] * bpool[e*64 + tid];
        bias[tid] = a;
    }

    const float* Xn = X + (size_t)n * BCDIM;
    const __nv_bfloat16* gWh = Wh + (size_t)n * (3*CC*HH);
    const __nv_bfloat16* gWl = Wl + (size_t)n * (3*CC*HH);

    const __nv_bfloat16* srcH[6];
    const __nv_bfloat16* srcL[6];
    int rstr[6];
    {
        srcH[0] = Xh   + (size_t)n * BCDIM;        srcL[0] = Xl   + (size_t)n * BCDIM;        rstr[0] = 128;
        srcH[1] = X2sh + (size_t)n * SHDIM;        srcL[1] = X2sl + (size_t)n * SHDIM;        rstr[1] = 64;
        srcH[2] = Yh   + (size_t)n * BCDIM;        srcL[2] = Yl   + (size_t)n * BCDIM;        rstr[2] = 128;
        srcH[3] = Ysh  + (size_t)n * SHDIM;        srcL[3] = Ysl  + (size_t)n * SHDIM;        rstr[3] = 64;
        srcH[4] = Yh   + (size_t)(NN+n) * BCDIM;   srcL[4] = Yl   + (size_t)(NN+n) * BCDIM;   rstr[4] = 128;
        srcH[5] = Ysh  + (size_t)(NN+n) * SHDIM;   srcL[5] = Ysl  + (size_t)(NN+n) * SHDIM;   rstr[5] = 64;
    }

    int wm = (wid >> 1) * 16, wn = (wid & 1) * 32;
    int g = lane >> 3, lr8 = lane & 7;

    float acc[4][4];
#pragma unroll
    for (int nt = 0; nt < 4; nt++)
#pragma unroll
        for (int q = 0; q < 4; q++) acc[nt][q] = 0.0f;

    for (int ck = 0; ck < 6; ck++) {
        {
            int kc0 = ck * 64;
#pragma unroll
            for (int q = 0; q < 2; q++) {
                int m = tid + q * 256;
                int kr = m >> 3, o8 = m & 7;
                uint32_t so = (uint32_t)(kr * 144 + o8 * 16);
                size_t eoff = (size_t)(kc0 + kr) * 64 + o8 * 8;
                cp_async16(sb + 18432 + so, gWh + eoff);
                cp_async16(sb + 27648 + so, gWl + eoff);
            }
        }
        {
            const __nv_bfloat16* ph = srcH[ck];
            const __nv_bfloat16* pl = srcL[ck];
            int str = rstr[ck];
#pragma unroll
            for (int q = 0; q < 2; q++) {
                int m = tid + q * 256;
                int r = m >> 3, c8 = m & 7;
                uint32_t so = (uint32_t)(r * 144 + c8 * 16);
                size_t eoff = (size_t)r * str + c8 * 8;
                cp_async16(sb + so, ph + eoff);
                cp_async16(sb + 9216 + so, pl + eoff);
            }
        }
        CP_COMMIT();
        CP_WAIT0();
        __syncthreads();

#pragma unroll
        for (int ks = 0; ks < 4; ks++) {
            uint32_t ahi[4], alo[4];
            uint32_t aad = (uint32_t)((wm + (g&1)*8 + lr8) * 144
                                      + (ks*16 + (g>>1)*8) * 2);
            ldsm_x4(ahi, sb + aad);
            ldsm_x4(alo, sb + 9216 + aad);
#pragma unroll
            for (int np = 0; np < 2; np++) {
                uint32_t bad = (uint32_t)((ks*16 + (g&1)*8 + lr8) * 144
                                          + (wn + np*16 + (g>>1)*8) * 2);
                uint32_t th[4], tl[4];
                ldsm_x4_t(th, sb + 18432 + bad);
                ldsm_x4_t(tl, sb + 27648 + bad);
                uint32_t b0h[2] = {th[0], th[1]}, b1h[2] = {th[2], th[3]};
                uint32_t b0l[2] = {tl[0], tl[1]}, b1l[2] = {tl[2], tl[3]};
                mma16816(acc[2*np],   ahi, b0h);
                mma16816(acc[2*np],   ahi, b0l);
                mma16816(acc[2*np],   alo, b0h);
                mma16816(acc[2*np+1], ahi, b1h);
                mma16816(acc[2*np+1], ahi, b1l);
                mma16816(acc[2*np+1], alo, b1h);
            }
        }
        __syncthreads();
    }

    const float* Rn = R + (size_t)n * SHDIM;
    int erow = lane >> 2, ecol = (lane & 3) * 2;
#pragma unroll
    for (int nt = 0; nt < 4; nt++) {
        int c = wn + nt*8 + ecol;
        float b0 = bias[c], b1 = bias[c+1];
#pragma unroll
        for (int h = 0; h < 2; h++) {
            int b = wm + erow + h*8;
            float hc0 = tanhf(acc[nt][h*2+0] + b0);
            float hc1 = tanhf(acc[nt][h*2+1] + b1);
            float2 r  = *(const float2*)(Rn + b*64 + c);
            float2 st = *(const float2*)(Xn + b*128 + 64 + c);
            float o0 = r.x * st.x + (1.0f - r.x) * hc0;
            float o1 = r.y * st.y + (1.0f - r.y) * hc1;
            *(float2*)(out + (size_t)b * (NN*HH) + n*HH + c) = make_float2(o0, o1);
        }
    }
}

// ---------------------------------------------------------------------------
extern "C" void kernel_launch(void* const* d_in, const int* in_sizes, int n_in,
                              void* d_out, int out_size) {
    const float* x     = (const float*)d_in[0];
    const float* state = (const float*)d_in[1];
    const float* E     = (const float*)d_in[2];
    const float* gWp   = (const float*)d_in[3];
    const float* gbp   = (const float*)d_in[4];
    const float* uWp   = (const float*)d_in[5];
    const float* ubp   = (const float*)d_in[6];
    float* out = (float*)d_out;

    float *X, *X2s, *R;
    __nv_bfloat16 *Xh, *Xl, *Yh, *Yl, *X2sh, *X2sl, *Ysh, *Ysl;
    __nv_bfloat16 *Ah, *Al, *Ath, *Atl, *Bt1, *Bt2, *Wh, *Wl, *Whu, *Wlu;
    cudaGetSymbolAddress((void**)&X,    g_X);
    cudaGetSymbolAddress((void**)&X2s,  g_X2s);
    cudaGetSymbolAddress((void**)&R,    g_R);
    cudaGetSymbolAddress((void**)&Xh,   g_Xh);
    cudaGetSymbolAddress((void**)&Xl,   g_Xl);
    cudaGetSymbolAddress((void**)&Yh,   g_Yh);
    cudaGetSymbolAddress((void**)&Yl,   g_Yl);
    cudaGetSymbolAddress((void**)&X2sh, g_X2sh);
    cudaGetSymbolAddress((void**)&X2sl, g_X2sl);
    cudaGetSymbolAddress((void**)&Ysh,  g_Ysh);
    cudaGetSymbolAddress((void**)&Ysl,  g_Ysl);
    cudaGetSymbolAddress((void**)&Ah,   g_Ah);
    cudaGetSymbolAddress((void**)&Al,   g_Al);
    cudaGetSymbolAddress((void**)&Ath,  g_Ath);
    cudaGetSymbolAddress((void**)&Atl,  g_Atl);
    cudaGetSymbolAddress((void**)&Bt1,  g_Bt1);
    cudaGetSymbolAddress((void**)&Bt2,  g_Bt2);
    cudaGetSymbolAddress((void**)&Wh,   g_Wh);
    cudaGetSymbolAddress((void**)&Wl,   g_Wl);
    cudaGetSymbolAddress((void**)&Whu,  g_Whu);
    cudaGetSymbolAddress((void**)&Wlu,  g_Wlu);

    cudaFuncSetAttribute(mma_gemm_kernel,
                         cudaFuncAttributeMaxDynamicSharedMemorySize, GEMM_SMEM);
    cudaFuncSetAttribute(pernode_gate_mma,
                         cudaFuncAttributeMaxDynamicSharedMemorySize, GATE_SMEM);
    cudaFuncSetAttribute(pernode_upd_mma,
                         cudaFuncAttributeMaxDynamicSharedMemorySize, UPD_SMEM);

    // fork side branches off the capture-origin stream
    cudaEventRecord(g_fork.fork, 0);
    cudaStreamWaitEvent(g_fork.s1, g_fork.fork, 0);
    cudaStreamWaitEvent(g_fork.s2, g_fork.fork, 0);

    // --- branch s1: adjacency, then A^2 (hi/lo epilogue into rows [NN,2NN))
    compute_A_kernel<<<NN, 256, 0, g_fork.s1>>>(E, Ah, Al, Ath, Atl);
    mma_gemm_kernel<<<dim3(NN/128, NN/128), 256, GEMM_SMEM, g_fork.s1>>>(
        Ah, Al, Ath, Atl, Ah + (size_t)NN*NN, Al + (size_t)NN*NN,
        nullptr, 1 << 30, NN, NN, NN);
    cudaEventRecord(g_fork.eA, g_fork.s1);

    // --- branch s2: per-node weight pools
    build_W_kernel<<<dim3(48, 64), 256, 0, g_fork.s2>>>(gWp, E, Wh, Wl, 3*CC*CC);
    cudaEventRecord(g_fork.eWg, g_fork.s2);
    build_W_kernel<<<dim3(24, 64), 256, 0, g_fork.s2>>>(uWp, E, Whu, Wlu, 3*CC*HH);
    cudaEventRecord(g_fork.eWu, g_fork.s2);

    // --- main branch (stream 0)
    build_X_fused_kernel<<<dim3(BCDIM/32, NN/32), dim3(32, 8)>>>(
        x, state, X, Xh, Xl, Bt1, Bt2);

    // GEMM1: [A;A^2] @ X^T, M=2048; rows >= NN get 2*acc - X combine; hi/lo out
    cudaStreamWaitEvent(0, g_fork.eA, 0);
    mma_gemm_kernel<<<dim3(BCDIM/128, 2*NN/128), 256, GEMM_SMEM>>>(
        Ah, Al, Bt1, Bt2, Yh, Yl, X, NN, 2*NN, BCDIM, NN);

    cudaStreamWaitEvent(0, g_fork.eWg, 0);
    pernode_gate_mma<<<NN, 256, GATE_SMEM>>>(
        X, Xh, Xl, Yh, Yl, Wh, Wl, E, gbp, X2s, X2sh, X2sl, R);

    // GEMM2: [A;A^2] @ X2s^T, N=4096; rows >= NN combined with X2s; hi/lo out
    transpose_split_kernel<<<dim3(SHDIM/32, NN/32), dim3(32, 8)>>>(X2s, Bt1, Bt2, SHDIM);
    mma_gemm_kernel<<<dim3(SHDIM/128, 2*NN/128), 256, GEMM_SMEM>>>(
        Ah, Al, Bt1, Bt2, Ysh, Ysl, X2s, NN, 2*NN, SHDIM, NN);

    cudaStreamWaitEvent(0, g_fork.eWu, 0);
    pernode_upd_mma<<<NN, 256, UPD_SMEM>>>(
        X, Xh, Xl, Yh, Yl, X2sh, X2sl, Ysh, Ysl, Whu, Wlu, E, ubp, R, out);
}

// round 11
// speedup vs baseline: 1.1060x; 1.0130x over previous
#include <cuda_runtime.h>
#include <cuda_bf16.h>
#include <cstdint>

#define NN 1024
#define BB 64
#define CC 128
#define HH 64
#define ED 16
#define BCDIM (BB*CC)   /* 8192 */
#define SHDIM (BB*HH)   /* 4096 */

// ---------------------------------------------------------------------------
// Device-global scratch
__device__ float g_X  [NN*BCDIM];                  // fp32 concat(x,state) [n, b*128+c]
__device__ float g_X2s[NN*SHDIM];                  // fp32 z*state compact [n, b*64+c]
__device__ float g_R  [NN*SHDIM];                  // r gate
__device__ __nv_bfloat16 g_Xh [NN*BCDIM];          // X hi/lo, [n, bc]
__device__ __nv_bfloat16 g_Xl [NN*BCDIM];
__device__ __nv_bfloat16 g_Yh [(size_t)2*NN*BCDIM]; // rows [0,NN): A@X ; [NN,2NN): 2*A^2@X - X
__device__ __nv_bfloat16 g_Yl [(size_t)2*NN*BCDIM];
__device__ __nv_bfloat16 g_X2sh[NN*SHDIM];
__device__ __nv_bfloat16 g_X2sl[NN*SHDIM];
__device__ __nv_bfloat16 g_Ysh[(size_t)2*NN*SHDIM]; // rows [0,NN): A@X2s ; [NN,2NN): combined
__device__ __nv_bfloat16 g_Ysl[(size_t)2*NN*SHDIM];
__device__ __nv_bfloat16 g_Ah [2*NN*NN];           // rows [0,NN): A hi; [NN,2NN): A^2 hi
__device__ __nv_bfloat16 g_Al [2*NN*NN];
__device__ __nv_bfloat16 g_Ath[NN*NN];
__device__ __nv_bfloat16 g_Atl[NN*NN];
__device__ __nv_bfloat16 g_Bt1[(size_t)BCDIM*NN];
__device__ __nv_bfloat16 g_Bt2[(size_t)BCDIM*NN];
__device__ __nv_bfloat16 g_Wh [(size_t)NN*3*CC*CC];
__device__ __nv_bfloat16 g_Wl [(size_t)NN*3*CC*CC];
__device__ __nv_bfloat16 g_Whu[(size_t)NN*3*CC*HH];
__device__ __nv_bfloat16 g_Wlu[(size_t)NN*3*CC*HH];

// ---------------------------------------------------------------------------
// Streams/events for graph-fork
struct ForkCtx {
    cudaStream_t s1, s2;
    cudaEvent_t fork, eA, eWg, eWu;
    ForkCtx() {
        cudaStreamCreateWithFlags(&s1, cudaStreamNonBlocking);
        cudaStreamCreateWithFlags(&s2, cudaStreamNonBlocking);
        cudaEventCreateWithFlags(&fork, cudaEventDisableTiming);
        cudaEventCreateWithFlags(&eA,   cudaEventDisableTiming);
        cudaEventCreateWithFlags(&eWg,  cudaEventDisableTiming);
        cudaEventCreateWithFlags(&eWu,  cudaEventDisableTiming);
    }
};
static ForkCtx g_fork;

// ---------------------------------------------------------------------------
// PTX helpers (sm_80-baseline only)
__device__ __forceinline__ uint32_t smem_to_u32(const void* p) {
    uint32_t a;
    asm("{ .reg .u64 t; cvta.to.shared.u64 t, %1; cvt.u32.u64 %0, t; }"
        : "=r"(a) : "l"(p));
    return a;
}
__device__ __forceinline__ void cp_async16(uint32_t dst, const void* src) {
    asm volatile("cp.async.cg.shared.global [%0], [%1], 16;" :: "r"(dst), "l"(src));
}
#define CP_COMMIT() asm volatile("cp.async.commit_group;" ::: "memory")
#define CP_WAIT0()  asm volatile("cp.async.wait_group 0;" ::: "memory")

__device__ __forceinline__ void ldsm_x4(uint32_t* r, uint32_t addr) {
    asm volatile("ldmatrix.sync.aligned.m8n8.x4.shared.b16 {%0,%1,%2,%3}, [%4];"
        : "=r"(r[0]), "=r"(r[1]), "=r"(r[2]), "=r"(r[3]) : "r"(addr));
}
__device__ __forceinline__ void ldsm_x4_t(uint32_t* r, uint32_t addr) {
    asm volatile("ldmatrix.sync.aligned.m8n8.x4.trans.shared.b16 {%0,%1,%2,%3}, [%4];"
        : "=r"(r[0]), "=r"(r[1]), "=r"(r[2]), "=r"(r[3]) : "r"(addr));
}
__device__ __forceinline__ void mma16816(float* d, const uint32_t* a, const uint32_t* b) {
    asm volatile(
        "mma.sync.aligned.m16n8k16.row.col.f32.bf16.bf16.f32 "
        "{%0,%1,%2,%3}, {%4,%5,%6,%7}, {%8,%9}, {%0,%1,%2,%3};"
        : "+f"(d[0]), "+f"(d[1]), "+f"(d[2]), "+f"(d[3])
        : "r"(a[0]), "r"(a[1]), "r"(a[2]), "r"(a[3]), "r"(b[0]), "r"(b[1]));
}
__device__ __forceinline__ uint32_t pack_split2(float a, float b, uint32_t* lo) {
    __nv_bfloat16 h0 = __float2bfloat16(a);
    __nv_bfloat16 h1 = __float2bfloat16(b);
    __nv_bfloat16 l0 = __float2bfloat16(a - __bfloat162float(h0));
    __nv_bfloat16 l1 = __float2bfloat16(b - __bfloat162float(h1));
    uint32_t hi;
    ((__nv_bfloat16*)&hi)[0] = h0; ((__nv_bfloat16*)&hi)[1] = h1;
    ((__nv_bfloat16*)lo)[0] = l0;  ((__nv_bfloat16*)lo)[1] = l1;
    return hi;
}

// ---------------------------------------------------------------------------
// build X fp32 + Xh/Xl [n,bc] + transposed Bt1/Bt2 [bc,n]
__global__ void build_X_fused_kernel(const float* __restrict__ x,
                                     const float* __restrict__ st,
                                     float* __restrict__ X,
                                     __nv_bfloat16* __restrict__ Xh,
                                     __nv_bfloat16* __restrict__ Xl,
                                     __nv_bfloat16* __restrict__ hi,
                                     __nv_bfloat16* __restrict__ lo) {
    __shared__ float t[32][33];
    int bc0 = blockIdx.x * 32;
    int n0  = blockIdx.y * 32;
    int tx = threadIdx.x, ty = threadIdx.y;
#pragma unroll
    for (int i = 0; i < 4; i++) {
        int n = n0 + ty + 8*i;
        int bc = bc0 + tx;
        int c = bc & 127, b = bc >> 7;
        float v = (c < HH) ? x [(size_t)b * (NN*HH) + n*HH + c]
                           : st[(size_t)b * (NN*HH) + n*HH + (c - HH)];
        size_t o = (size_t)n * BCDIM + bc;
        X[o] = v;
        __nv_bfloat16 h = __float2bfloat16(v);
        Xh[o] = h;
        Xl[o] = __float2bfloat16(v - __bfloat162float(h));
        t[ty + 8*i][tx] = v;
    }
    __syncthreads();
#pragma unroll
    for (int i = 0; i < 4; i++) {
        float v = t[tx][ty + 8*i];
        __nv_bfloat16 h = __float2bfloat16(v);
        size_t o = (size_t)(bc0 + ty + 8*i) * NN + n0 + tx;
        hi[o] = h;
        lo[o] = __float2bfloat16(v - __bfloat162float(h));
    }
}

// ---------------------------------------------------------------------------
__global__ void compute_A_kernel(const float* __restrict__ E,
                                 __nv_bfloat16* __restrict__ Ah,
                                 __nv_bfloat16* __restrict__ Al,
                                 __nv_bfloat16* __restrict__ Ath,
                                 __nv_bfloat16* __restrict__ Atl) {
    int i = blockIdx.x;
    int tid = threadIdx.x;
    __shared__ float Ei[ED];
    __shared__ float red[256];
    if (tid < ED) Ei[tid] = E[i*ED + tid];
    __syncthreads();

    float v[4];
    float vmax = 0.0f;
#pragma unroll
    for (int p = 0; p < 4; p++) {
        int j = tid + p * 256;
        const float4* Ej = (const float4*)(E + (size_t)j * ED);
        float4 e0 = Ej[0], e1 = Ej[1], e2 = Ej[2], e3 = Ej[3];
        float d = Ei[0]*e0.x + Ei[1]*e0.y + Ei[2]*e0.z + Ei[3]*e0.w
                + Ei[4]*e1.x + Ei[5]*e1.y + Ei[6]*e1.z + Ei[7]*e1.w
                + Ei[8]*e2.x + Ei[9]*e2.y + Ei[10]*e2.z + Ei[11]*e2.w
                + Ei[12]*e3.x + Ei[13]*e3.y + Ei[14]*e3.z + Ei[15]*e3.w;
        d = fmaxf(d, 0.0f);
        v[p] = d;
        vmax = fmaxf(vmax, d);
    }
    red[tid] = vmax; __syncthreads();
    for (int s = 128; s > 0; s >>= 1) {
        if (tid < s) red[tid] = fmaxf(red[tid], red[tid + s]);
        __syncthreads();
    }
    vmax = red[0];
    __syncthreads();
    float lsum = 0.0f;
#pragma unroll
    for (int p = 0; p < 4; p++) { v[p] = __expf(v[p] - vmax); lsum += v[p]; }
    red[tid] = lsum; __syncthreads();
    for (int s = 128; s > 0; s >>= 1) {
        if (tid < s) red[tid] += red[tid + s];
        __syncthreads();
    }
    float inv = 1.0f / red[0];
#pragma unroll
    for (int p = 0; p < 4; p++) {
        int j = tid + p * 256;
        float a = v[p] * inv;
        __nv_bfloat16 h = __float2bfloat16(a);
        __nv_bfloat16 l = __float2bfloat16(a - __bfloat162float(h));
        Ah [(size_t)i * NN + j] = h;
        Al [(size_t)i * NN + j] = l;
        Ath[(size_t)j * NN + i] = h;
        Atl[(size_t)j * NN + i] = l;
    }
}

// ---------------------------------------------------------------------------
// transpose + split: src fp32 [NN, W] -> hi/lo bf16 [W, NN]
__global__ void transpose_split_kernel(const float* __restrict__ src,
                                       __nv_bfloat16* __restrict__ hi,
                                       __nv_bfloat16* __restrict__ lo, int W) {
    __shared__ float t[32][33];
    int m0 = blockIdx.x * 32;
    int n0 = blockIdx.y * 32;
    int tx = threadIdx.x, ty = threadIdx.y;
#pragma unroll
    for (int i = 0; i < 4; i++)
        t[ty + 8*i][tx] = src[(size_t)(n0 + ty + 8*i) * W + m0 + tx];
    __syncthreads();
#pragma unroll
    for (int i = 0; i < 4; i++) {
        float v = t[tx][ty + 8*i];
        __nv_bfloat16 h = __float2bfloat16(v);
        size_t o = (size_t)(m0 + ty + 8*i) * NN + n0 + tx;
        hi[o] = h;
        lo[o] = __float2bfloat16(v - __bfloat162float(h));
    }
}

// ---------------------------------------------------------------------------
// Big bf16x3 GEMM, 3-stage cp.async pipeline, one barrier per K-chunk.
// acc = (Ahi+Alo) @ (Bhi+Blo)^T.
// Epilogue: if block_row >= comb_start, acc = 2*acc - Xref[row-comb_start];
// always written as bf16 hi/lo split to Ch/Cl.
#define GSTRIDE 144
#define HALF_BYTES (128*GSTRIDE)
#define STAGE_BYTES (4*HALF_BYTES)
#define GEMM_SMEM (3*STAGE_BYTES)   /* 221184 bytes, 3 stages */

__global__ __launch_bounds__(256, 1)
void mma_gemm_kernel(const __nv_bfloat16* __restrict__ Ahi,
                     const __nv_bfloat16* __restrict__ Alo,
                     const __nv_bfloat16* __restrict__ Bhi,
                     const __nv_bfloat16* __restrict__ Blo,
                     __nv_bfloat16* __restrict__ Ch,
                     __nv_bfloat16* __restrict__ Cl,
                     const float* __restrict__ Xref, int comb_start,
                     int M, int N, int K) {
    extern __shared__ char smem[];
    uint32_t sb = smem_to_u32(smem);
    int tid = threadIdx.x;
    int lane = tid & 31, wid = tid >> 5;
    int wm = (wid >> 1) * 32;
    int wn = (wid & 1) * 64;
    int block_row = blockIdx.y * 128;
    int block_col = blockIdx.x * 128;

    const char* gA0 = (const char*)(Ahi + (size_t)block_row * K);
    const char* gA1 = (const char*)(Alo + (size_t)block_row * K);
    const char* gB0 = (const char*)(Bhi + (size_t)block_col * K);
    const char* gB1 = (const char*)(Blo + (size_t)block_col * K);

    int lr_ = tid >> 3;
    int lc_ = (tid & 7) * 16;

    float acc[2][8][4];
#pragma unroll
    for (int mt = 0; mt < 2; mt++)
#pragma unroll
        for (int nt = 0; nt < 8; nt++)
#pragma unroll
            for (int q = 0; q < 4; q++) acc[mt][nt][q] = 0.0f;

    int g = lane >> 3;
    int lr8 = lane & 7;
    int a_row = wm + (g & 1) * 8 + lr8;
    int a_kc  = (g >> 1) * 8;
    int b_row = wn + (g >> 1) * 8 + lr8;
    int b_kc  = (g & 1) * 8;

    int nstages = K >> 6;

    auto load_stage = [&](int st, int kt) {
        uint32_t base = sb + st * STAGE_BYTES;
        size_t k0b = (size_t)(kt * 64) * 2;
#pragma unroll
        for (int q = 0; q < 4; q++) {
            int r = lr_ + q * 32;
            uint32_t so = (uint32_t)(r * GSTRIDE + lc_);
            size_t go = (size_t)r * (K * 2) + k0b + lc_;
            cp_async16(base + 0*HALF_BYTES + so, gA0 + go);
            cp_async16(base + 1*HALF_BYTES + so, gA1 + go);
            cp_async16(base + 2*HALF_BYTES + so, gB0 + go);
            cp_async16(base + 3*HALF_BYTES + so, gB1 + go);
        }
        CP_COMMIT();
    };

    // prologue: two stages in flight
    load_stage(0, 0);
    if (nstages > 1) load_stage(1, 1);

    for (int kt = 0; kt < nstages; kt++) {
        int st = kt % 3;
        if (kt + 1 < nstages) {
            asm volatile("cp.async.wait_group 1;" ::: "memory");
        } else {
            CP_WAIT0();
        }
        __syncthreads();
        // issue load for kt+2 into buffer (kt+2)%3 (safe: compute of kt-1 done)
        if (kt + 2 < nstages) load_stage((kt + 2) % 3, kt + 2);

        uint32_t aHiB = sb + st * STAGE_BYTES;
        uint32_t aLoB = aHiB + HALF_BYTES;
        uint32_t bHiB = aLoB + HALF_BYTES;
        uint32_t bLoB = bHiB + HALF_BYTES;

#pragma unroll
        for (int ks = 0; ks < 4; ks++) {
            int kc = ks * 16;
            uint32_t ahi[2][4], alo[2][4];
#pragma unroll
            for (int mt = 0; mt < 2; mt++) {
                uint32_t ad = (uint32_t)((a_row + mt*16) * GSTRIDE + (kc + a_kc) * 2);
                ldsm_x4(ahi[mt], aHiB + ad);
                ldsm_x4(alo[mt], aLoB + ad);
            }
            uint32_t bhi[8][2], blo[8][2];
#pragma unroll
            for (int np = 0; np < 4; np++) {
                uint32_t bd = (uint32_t)((b_row + np*16) * GSTRIDE + (kc + b_kc) * 2);
                uint32_t t[4];
                ldsm_x4(t, bHiB + bd);
                bhi[2*np][0] = t[0]; bhi[2*np][1] = t[1];
                bhi[2*np+1][0] = t[2]; bhi[2*np+1][1] = t[3];
                ldsm_x4(t, bLoB + bd);
                blo[2*np][0] = t[0]; blo[2*np][1] = t[1];
                blo[2*np+1][0] = t[2]; blo[2*np+1][1] = t[3];
            }
#pragma unroll
            for (int mt = 0; mt < 2; mt++)
#pragma unroll
                for (int nt = 0; nt < 8; nt++) {
                    mma16816(acc[mt][nt], ahi[mt], bhi[nt]);
                    mma16816(acc[mt][nt], ahi[mt], blo[nt]);
                    mma16816(acc[mt][nt], alo[mt], bhi[nt]);
                }
        }
        // no trailing barrier: next iteration's wait+sync protects buffers
    }

    int erow = lane >> 2, ecol = (lane & 3) * 2;
    bool comb = (block_row >= comb_start);
#pragma unroll
    for (int mt = 0; mt < 2; mt++) {
#pragma unroll
        for (int nt = 0; nt < 8; nt++) {
            size_t cc = (size_t)block_col + wn + nt*8 + ecol;
#pragma unroll
            for (int h = 0; h < 2; h++) {
                size_t row = (size_t)block_row + wm + mt*16 + erow + h*8;
                float v0 = acc[mt][nt][h*2+0];
                float v1 = acc[mt][nt][h*2+1];
                if (comb) {
                    const float* xr = Xref + (row - comb_start) * N + cc;
                    v0 = 2.0f*v0 - xr[0];
                    v1 = 2.0f*v1 - xr[1];
                }
                uint32_t lo;
                uint32_t hi = pack_split2(v0, v1, &lo);
                *(uint32_t*)(Ch + row * N + cc) = hi;
                *(uint32_t*)(Cl + row * N + cc) = lo;
            }
        }
    }
}

// ---------------------------------------------------------------------------
// W[n,:] = sum_e E[n,e] * Wp[e,:], output bf16 hi/lo (4-node groups: low regs)
__global__ __launch_bounds__(256)
void build_W_kernel(const float* __restrict__ Wp,
                    const float* __restrict__ E,
                    __nv_bfloat16* __restrict__ Wh,
                    __nv_bfloat16* __restrict__ Wl, int TC) {
    int ng = blockIdx.y;
    int cbase = blockIdx.x * 1024;
    __shared__ float Es[16][16];
    {
        int nn = threadIdx.x >> 4, e = threadIdx.x & 15;
        if (threadIdx.x < 256) Es[nn][e] = E[(ng * 16 + nn) * ED + e];
    }
    __syncthreads();
#pragma unroll 1
    for (int cc = 0; cc < 1024; cc += 256) {
        int c = cbase + cc + threadIdx.x;
        float wp[16];
#pragma unroll
        for (int e = 0; e < 16; e++) wp[e] = Wp[(size_t)e * TC + c];
#pragma unroll 1
        for (int nn0 = 0; nn0 < 16; nn0 += 4) {
#pragma unroll
            for (int k = 0; k < 4; k++) {
                int nn = nn0 + k;
                float a = 0.0f;
#pragma unroll
                for (int e = 0; e < 16; e++) a += Es[nn][e] * wp[e];
                __nv_bfloat16 h = __float2bfloat16(a);
                size_t o = (size_t)(ng * 16 + nn) * TC + c;
                Wh[o] = h;
                Wl[o] = __float2bfloat16(a - __bfloat162float(h));
            }
        }
    }
}

// ---------------------------------------------------------------------------
// Per-node GATE: pure cp.async -> ldsm -> mma (all operands pre-split bf16).
// smem: XH +0 (64x144B), XL +9216, WH +18432 (64x272B), WL +35840, bias +53248.
#define GATE_SMEM 53760
__global__ __launch_bounds__(256)
void pernode_gate_mma(const float* __restrict__ X,
                      const __nv_bfloat16* __restrict__ Xh,
                      const __nv_bfloat16* __restrict__ Xl,
                      const __nv_bfloat16* __restrict__ Yh,
                      const __nv_bfloat16* __restrict__ Yl,
                      const __nv_bfloat16* __restrict__ Wh,
                      const __nv_bfloat16* __restrict__ Wl,
                      const float* __restrict__ E, const float* __restrict__ bpool,
                      float* __restrict__ X2s,
                      __nv_bfloat16* __restrict__ X2sh,
                      __nv_bfloat16* __restrict__ X2sl,
                      float* __restrict__ R) {
    extern __shared__ char sm[];
    uint32_t sb = smem_to_u32(sm);
    float* bias = (float*)(sm + 53248);
    int n = blockIdx.x;
    int tid = threadIdx.x, lane = tid & 31, wid = tid >> 5;

    if (tid < 128) {
        float a = 0.0f;
#pragma unroll
        for (int e = 0; e < 16; e++) a += E[n*ED + e] * bpool[e*128 + tid];
        bias[tid] = a;
    }

    const float* Xn = X + (size_t)n * BCDIM;
    const __nv_bfloat16* gWh = Wh + (size_t)n * (3*CC*CC);
    const __nv_bfloat16* gWl = Wl + (size_t)n * (3*CC*CC);

    const __nv_bfloat16* srcH[6];
    const __nv_bfloat16* srcL[6];
    {
        const __nv_bfloat16* xh = Xh + (size_t)n * BCDIM;
        const __nv_bfloat16* xl = Xl + (size_t)n * BCDIM;
        const __nv_bfloat16* y1h = Yh + (size_t)n * BCDIM;
        const __nv_bfloat16* y1l = Yl + (size_t)n * BCDIM;
        const __nv_bfloat16* y2h = Yh + (size_t)(NN + n) * BCDIM;
        const __nv_bfloat16* y2l = Yl + (size_t)(NN + n) * BCDIM;
        srcH[0] = xh;      srcL[0] = xl;
        srcH[1] = xh + 64; srcL[1] = xl + 64;
        srcH[2] = y1h;     srcL[2] = y1l;
        srcH[3] = y1h + 64; srcL[3] = y1l + 64;
        srcH[4] = y2h;     srcL[4] = y2l;
        srcH[5] = y2h + 64; srcL[5] = y2l + 64;
    }

    int wm = (wid >> 1) * 16, wn = (wid & 1) * 64;
    int g = lane >> 3, lr8 = lane & 7;

    float acc[8][4];
#pragma unroll
    for (int nt = 0; nt < 8; nt++)
#pragma unroll
        for (int q = 0; q < 4; q++) acc[nt][q] = 0.0f;

    for (int ck = 0; ck < 6; ck++) {
        {
            int kc0 = ck * 64;
#pragma unroll
            for (int q = 0; q < 4; q++) {
                int m = tid + q * 256;
                int kr = m >> 4, o8 = m & 15;
                uint32_t so = (uint32_t)(kr * 272 + o8 * 16);
                size_t eoff = (size_t)(kc0 + kr) * 128 + o8 * 8;
                cp_async16(sb + 18432 + so, gWh + eoff);
                cp_async16(sb + 35840 + so, gWl + eoff);
            }
        }
        {
            const __nv_bfloat16* ph = srcH[ck];
            const __nv_bfloat16* pl = srcL[ck];
#pragma unroll
            for (int q = 0; q < 2; q++) {
                int m = tid + q * 256;
                int r = m >> 3, c8 = m & 7;
                uint32_t so = (uint32_t)(r * 144 + c8 * 16);
                size_t eoff = (size_t)r * 128 + c8 * 8;
                cp_async16(sb + so, ph + eoff);
                cp_async16(sb + 9216 + so, pl + eoff);
            }
        }
        CP_COMMIT();
        CP_WAIT0();
        __syncthreads();

#pragma unroll
        for (int ks = 0; ks < 4; ks++) {
            uint32_t ahi[4], alo[4];
            uint32_t aad = (uint32_t)((wm + (g&1)*8 + lr8) * 144
                                      + (ks*16 + (g>>1)*8) * 2);
            ldsm_x4(ahi, sb + aad);
            ldsm_x4(alo, sb + 9216 + aad);
#pragma unroll
            for (int np = 0; np < 4; np++) {
                uint32_t bad = (uint32_t)((ks*16 + (g&1)*8 + lr8) * 272
                                          + (wn + np*16 + (g>>1)*8) * 2);
                uint32_t th[4], tl[4];
                ldsm_x4_t(th, sb + 18432 + bad);
                ldsm_x4_t(tl, sb + 35840 + bad);
                uint32_t b0h[2] = {th[0], th[1]}, b1h[2] = {th[2], th[3]};
                uint32_t b0l[2] = {tl[0], tl[1]}, b1l[2] = {tl[2], tl[3]};
                mma16816(acc[2*np],   ahi, b0h);
                mma16816(acc[2*np],   ahi, b0l);
                mma16816(acc[2*np],   alo, b0h);
                mma16816(acc[2*np+1], ahi, b1h);
                mma16816(acc[2*np+1], ahi, b1l);
                mma16816(acc[2*np+1], alo, b1h);
            }
        }
        __syncthreads();
    }

    float* X2sn = X2s + (size_t)n * SHDIM;
    __nv_bfloat16* X2shn = X2sh + (size_t)n * SHDIM;
    __nv_bfloat16* X2sln = X2sl + (size_t)n * SHDIM;
    float* Rn = R + (size_t)n * SHDIM;
    int erow = lane >> 2, ecol = (lane & 3) * 2;
    bool isz = ((wid & 1) == 0);
#pragma unroll
    for (int nt = 0; nt < 8; nt++) {
        int c = wn + nt*8 + ecol;
        float b0 = bias[c], b1 = bias[c+1];
#pragma unroll
        for (int h = 0; h < 2; h++) {
            int b = wm + erow + h*8;
            float s0 = 1.0f / (1.0f + __expf(-(acc[nt][h*2+0] + b0)));
            float s1 = 1.0f / (1.0f + __expf(-(acc[nt][h*2+1] + b1)));
            if (isz) {
                float2 st = *(const float2*)(Xn + b*128 + 64 + c);
                float z0 = s0 * st.x, z1 = s1 * st.y;
                *(float2*)(X2sn + b*64 + c) = make_float2(z0, z1);
                uint32_t lo;
                uint32_t hi = pack_split2(z0, z1, &lo);
                *(uint32_t*)(X2shn + b*64 + c) = hi;
                *(uint32_t*)(X2sln + b*64 + c) = lo;
            } else {
                *(float2*)(Rn + b*64 + (c - 64)) = make_float2(s0, s1);
            }
        }
    }
}

// ---------------------------------------------------------------------------
// Per-node UPDATE: pure cp.async -> ldsm -> mma + GRU combine.
// smem: XH +0, XL +9216, WH +18432 (64x144B), WL +27648, bias +36864.
#define UPD_SMEM 37120
__global__ __launch_bounds__(256)
void pernode_upd_mma(const float* __restrict__ X,
                     const __nv_bfloat16* __restrict__ Xh,
                     const __nv_bfloat16* __restrict__ Xl,
                     const __nv_bfloat16* __restrict__ Yh,
                     const __nv_bfloat16* __restrict__ Yl,
                     const __nv_bfloat16* __restrict__ X2sh,
                     const __nv_bfloat16* __restrict__ X2sl,
                     const __nv_bfloat16* __restrict__ Ysh,
                     const __nv_bfloat16* __restrict__ Ysl,
                     const __nv_bfloat16* __restrict__ Wh,
                     const __nv_bfloat16* __restrict__ Wl,
                     const float* __restrict__ E, const float* __restrict__ bpool,
                     const float* __restrict__ R, float* __restrict__ out) {
    extern __shared__ char sm[];
    uint32_t sb = smem_to_u32(sm);
    float* bias = (float*)(sm + 36864);
    int n = blockIdx.x;
    int tid = threadIdx.x, lane = tid & 31, wid = tid >> 5;

    if (tid < 64) {
        float a = 0.0f;
#pragma unroll
        for (int e = 0; e < 16; e++) a += E[n*ED + e] * bpool[e*64 + tid];
        bias[tid] = a;
    }

    const float* Xn = X + (size_t)n * BCDIM;
    const __nv_bfloat16* gWh = Wh + (size_t)n * (3*CC*HH);
    const __nv_bfloat16* gWl = Wl + (size_t)n * (3*CC*HH);

    const __nv_bfloat16* srcH[6];
    const __nv_bfloat16* srcL[6];
    int rstr[6];
    {
        srcH[0] = Xh   + (size_t)n * BCDIM;        srcL[0] = Xl   + (size_t)n * BCDIM;        rstr[0] = 128;
        srcH[1] = X2sh + (size_t)n * SHDIM;        srcL[1] = X2sl + (size_t)n * SHDIM;        rstr[1] = 64;
        srcH[2] = Yh   + (size_t)n * BCDIM;        srcL[2] = Yl   + (size_t)n * BCDIM;        rstr[2] = 128;
        srcH[3] = Ysh  + (size_t)n * SHDIM;        srcL[3] = Ysl  + (size_t)n * SHDIM;        rstr[3] = 64;
        srcH[4] = Yh   + (size_t)(NN+n) * BCDIM;   srcL[4] = Yl   + (size_t)(NN+n) * BCDIM;   rstr[4] = 128;
        srcH[5] = Ysh  + (size_t)(NN+n) * SHDIM;   srcL[5] = Ysl  + (size_t)(NN+n) * SHDIM;   rstr[5] = 64;
    }

    int wm = (wid >> 1) * 16, wn = (wid & 1) * 32;
    int g = lane >> 3, lr8 = lane & 7;

    float acc[4][4];
#pragma unroll
    for (int nt = 0; nt < 4; nt++)
#pragma unroll
        for (int q = 0; q < 4; q++) acc[nt][q] = 0.0f;

    for (int ck = 0; ck < 6; ck++) {
        {
            int kc0 = ck * 64;
#pragma unroll
            for (int q = 0; q < 2; q++) {
                int m = tid + q * 256;
                int kr = m >> 3, o8 = m & 7;
                uint32_t so = (uint32_t)(kr * 144 + o8 * 16);
                size_t eoff = (size_t)(kc0 + kr) * 64 + o8 * 8;
                cp_async16(sb + 18432 + so, gWh + eoff);
                cp_async16(sb + 27648 + so, gWl + eoff);
            }
        }
        {
            const __nv_bfloat16* ph = srcH[ck];
            const __nv_bfloat16* pl = srcL[ck];
            int str = rstr[ck];
#pragma unroll
            for (int q = 0; q < 2; q++) {
                int m = tid + q * 256;
                int r = m >> 3, c8 = m & 7;
                uint32_t so = (uint32_t)(r * 144 + c8 * 16);
                size_t eoff = (size_t)r * str + c8 * 8;
                cp_async16(sb + so, ph + eoff);
                cp_async16(sb + 9216 + so, pl + eoff);
            }
        }
        CP_COMMIT();
        CP_WAIT0();
        __syncthreads();

#pragma unroll
        for (int ks = 0; ks < 4; ks++) {
            uint32_t ahi[4], alo[4];
            uint32_t aad = (uint32_t)((wm + (g&1)*8 + lr8) * 144
                                      + (ks*16 + (g>>1)*8) * 2);
            ldsm_x4(ahi, sb + aad);
            ldsm_x4(alo, sb + 9216 + aad);
#pragma unroll
            for (int np = 0; np < 2; np++) {
                uint32_t bad = (uint32_t)((ks*16 + (g&1)*8 + lr8) * 144
                                          + (wn + np*16 + (g>>1)*8) * 2);
                uint32_t th[4], tl[4];
                ldsm_x4_t(th, sb + 18432 + bad);
                ldsm_x4_t(tl, sb + 27648 + bad);
                uint32_t b0h[2] = {th[0], th[1]}, b1h[2] = {th[2], th[3]};
                uint32_t b0l[2] = {tl[0], tl[1]}, b1l[2] = {tl[2], tl[3]};
                mma16816(acc[2*np],   ahi, b0h);
                mma16816(acc[2*np],   ahi, b0l);
                mma16816(acc[2*np],   alo, b0h);
                mma16816(acc[2*np+1], ahi, b1h);
                mma16816(acc[2*np+1], ahi, b1l);
                mma16816(acc[2*np+1], alo, b1h);
            }
        }
        __syncthreads();
    }

    const float* Rn = R + (size_t)n * SHDIM;
    int erow = lane >> 2, ecol = (lane & 3) * 2;
#pragma unroll
    for (int nt = 0; nt < 4; nt++) {
        int c = wn + nt*8 + ecol;
        float b0 = bias[c], b1 = bias[c+1];
#pragma unroll
        for (int h = 0; h < 2; h++) {
            int b = wm + erow + h*8;
            float hc0 = tanhf(acc[nt][h*2+0] + b0);
            float hc1 = tanhf(acc[nt][h*2+1] + b1);
            float2 r  = *(const float2*)(Rn + b*64 + c);
            float2 st = *(const float2*)(Xn + b*128 + 64 + c);
            float o0 = r.x * st.x + (1.0f - r.x) * hc0;
            float o1 = r.y * st.y + (1.0f - r.y) * hc1;
            *(float2*)(out + (size_t)b * (NN*HH) + n*HH + c) = make_float2(o0, o1);
        }
    }
}

// ---------------------------------------------------------------------------
extern "C" void kernel_launch(void* const* d_in, const int* in_sizes, int n_in,
                              void* d_out, int out_size) {
    const float* x     = (const float*)d_in[0];
    const float* state = (const float*)d_in[1];
    const float* E     = (const float*)d_in[2];
    const float* gWp   = (const float*)d_in[3];
    const float* gbp   = (const float*)d_in[4];
    const float* uWp   = (const float*)d_in[5];
    const float* ubp   = (const float*)d_in[6];
    float* out = (float*)d_out;

    float *X, *X2s, *R;
    __nv_bfloat16 *Xh, *Xl, *Yh, *Yl, *X2sh, *X2sl, *Ysh, *Ysl;
    __nv_bfloat16 *Ah, *Al, *Ath, *Atl, *Bt1, *Bt2, *Wh, *Wl, *Whu, *Wlu;
    cudaGetSymbolAddress((void**)&X,    g_X);
    cudaGetSymbolAddress((void**)&X2s,  g_X2s);
    cudaGetSymbolAddress((void**)&R,    g_R);
    cudaGetSymbolAddress((void**)&Xh,   g_Xh);
    cudaGetSymbolAddress((void**)&Xl,   g_Xl);
    cudaGetSymbolAddress((void**)&Yh,   g_Yh);
    cudaGetSymbolAddress((void**)&Yl,   g_Yl);
    cudaGetSymbolAddress((void**)&X2sh, g_X2sh);
    cudaGetSymbolAddress((void**)&X2sl, g_X2sl);
    cudaGetSymbolAddress((void**)&Ysh,  g_Ysh);
    cudaGetSymbolAddress((void**)&Ysl,  g_Ysl);
    cudaGetSymbolAddress((void**)&Ah,   g_Ah);
    cudaGetSymbolAddress((void**)&Al,   g_Al);
    cudaGetSymbolAddress((void**)&Ath,  g_Ath);
    cudaGetSymbolAddress((void**)&Atl,  g_Atl);
    cudaGetSymbolAddress((void**)&Bt1,  g_Bt1);
    cudaGetSymbolAddress((void**)&Bt2,  g_Bt2);
    cudaGetSymbolAddress((void**)&Wh,   g_Wh);
    cudaGetSymbolAddress((void**)&Wl,   g_Wl);
    cudaGetSymbolAddress((void**)&Whu,  g_Whu);
    cudaGetSymbolAddress((void**)&Wlu,  g_Wlu);

    cudaFuncSetAttribute(mma_gemm_kernel,
                         cudaFuncAttributeMaxDynamicSharedMemorySize, GEMM_SMEM);
    cudaFuncSetAttribute(pernode_gate_mma,
                         cudaFuncAttributeMaxDynamicSharedMemorySize, GATE_SMEM);
    cudaFuncSetAttribute(pernode_upd_mma,
                         cudaFuncAttributeMaxDynamicSharedMemorySize, UPD_SMEM);

    // fork side branches off the capture-origin stream
    cudaEventRecord(g_fork.fork, 0);
    cudaStreamWaitEvent(g_fork.s1, g_fork.fork, 0);
    cudaStreamWaitEvent(g_fork.s2, g_fork.fork, 0);

    // --- branch s1: adjacency, then A^2 (hi/lo epilogue into rows [NN,2NN))
    compute_A_kernel<<<NN, 256, 0, g_fork.s1>>>(E, Ah, Al, Ath, Atl);
    mma_gemm_kernel<<<dim3(NN/128, NN/128), 256, GEMM_SMEM, g_fork.s1>>>(
        Ah, Al, Ath, Atl, Ah + (size_t)NN*NN, Al + (size_t)NN*NN,
        nullptr, 1 << 30, NN, NN, NN);
    cudaEventRecord(g_fork.eA, g_fork.s1);

    // --- branch s2: per-node weight pools
    build_W_kernel<<<dim3(48, 64), 256, 0, g_fork.s2>>>(gWp, E, Wh, Wl, 3*CC*CC);
    cudaEventRecord(g_fork.eWg, g_fork.s2);
    build_W_kernel<<<dim3(24, 64), 256, 0, g_fork.s2>>>(uWp, E, Whu, Wlu, 3*CC*HH);
    cudaEventRecord(g_fork.eWu, g_fork.s2);

    // --- main branch (stream 0)
    build_X_fused_kernel<<<dim3(BCDIM/32, NN/32), dim3(32, 8)>>>(
        x, state, X, Xh, Xl, Bt1, Bt2);

    // GEMM1: [A;A^2] @ X^T, M=2048; rows >= NN get 2*acc - X combine; hi/lo out
    cudaStreamWaitEvent(0, g_fork.eA, 0);
    mma_gemm_kernel<<<dim3(BCDIM/128, 2*NN/128), 256, GEMM_SMEM>>>(
        Ah, Al, Bt1, Bt2, Yh, Yl, X, NN, 2*NN, BCDIM, NN);

    cudaStreamWaitEvent(0, g_fork.eWg, 0);
    pernode_gate_mma<<<NN, 256, GATE_SMEM>>>(
        X, Xh, Xl, Yh, Yl, Wh, Wl, E, gbp, X2s, X2sh, X2sl, R);

    // GEMM2: [A;A^2] @ X2s^T, N=4096; rows >= NN combined with X2s; hi/lo out
    transpose_split_kernel<<<dim3(SHDIM/32, NN/32), dim3(32, 8)>>>(X2s, Bt1, Bt2, SHDIM);
    mma_gemm_kernel<<<dim3(SHDIM/128, 2*NN/128), 256, GEMM_SMEM>>>(
        Ah, Al, Bt1, Bt2, Ysh, Ysl, X2s, NN, 2*NN, SHDIM, NN);

    cudaStreamWaitEvent(0, g_fork.eWu, 0);
    pernode_upd_mma<<<NN, 256, UPD_SMEM>>>(
        X, Xh, Xl, Yh, Yl, X2sh, X2sl, Ysh, Ysl, Whu, Wlu, E, ubp, R, out);
}

// round 14
// speedup vs baseline: 1.1147x; 1.0079x over previous
#include <cuda_runtime.h>
#include <cuda_bf16.h>
#include <cstdint>

#define NN 1024
#define BB 64
#define CC 128
#define HH 64
#define ED 16
#define BCDIM (BB*CC)   /* 8192 */
#define SHDIM (BB*HH)   /* 4096 */

// ---------------------------------------------------------------------------
// Device-global scratch
__device__ float g_X  [NN*BCDIM];                  // fp32 concat(x,state) [n, b*128+c]
__device__ float g_X2s[NN*SHDIM];                  // fp32 z*state compact [n, b*64+c]
__device__ float g_R  [NN*SHDIM];                  // r gate
__device__ float g_Af [NN*NN];                     // fp32 adjacency (row-major)
__device__ __nv_bfloat16 g_Xh [NN*BCDIM];          // X hi/lo, [n, bc]
__device__ __nv_bfloat16 g_Xl [NN*BCDIM];
__device__ __nv_bfloat16 g_Yh [(size_t)2*NN*BCDIM]; // rows [0,NN): A@X ; [NN,2NN): 2*A^2@X - X
__device__ __nv_bfloat16 g_Yl [(size_t)2*NN*BCDIM];
__device__ __nv_bfloat16 g_X2sh[NN*SHDIM];
__device__ __nv_bfloat16 g_X2sl[NN*SHDIM];
__device__ __nv_bfloat16 g_Ysh[(size_t)2*NN*SHDIM]; // rows [0,NN): A@X2s ; [NN,2NN): combined
__device__ __nv_bfloat16 g_Ysl[(size_t)2*NN*SHDIM];
__device__ __nv_bfloat16 g_Ah [2*NN*NN];           // rows [0,NN): A hi; [NN,2NN): A^2 hi
__device__ __nv_bfloat16 g_Al [2*NN*NN];
__device__ __nv_bfloat16 g_Ath[NN*NN];
__device__ __nv_bfloat16 g_Atl[NN*NN];
__device__ __nv_bfloat16 g_Bt1[(size_t)BCDIM*NN];
__device__ __nv_bfloat16 g_Bt2[(size_t)BCDIM*NN];
__device__ __nv_bfloat16 g_Wh [(size_t)NN*3*CC*CC];
__device__ __nv_bfloat16 g_Wl [(size_t)NN*3*CC*CC];
__device__ __nv_bfloat16 g_Whu[(size_t)NN*3*CC*HH];
__device__ __nv_bfloat16 g_Wlu[(size_t)NN*3*CC*HH];

// ---------------------------------------------------------------------------
// Streams/events for graph-fork
struct ForkCtx {
    cudaStream_t s1, s2;
    cudaEvent_t fork, eA0, eA, eWg, eWu;
    ForkCtx() {
        cudaStreamCreateWithFlags(&s1, cudaStreamNonBlocking);
        cudaStreamCreateWithFlags(&s2, cudaStreamNonBlocking);
        cudaEventCreateWithFlags(&fork, cudaEventDisableTiming);
        cudaEventCreateWithFlags(&eA0,  cudaEventDisableTiming);
        cudaEventCreateWithFlags(&eA,   cudaEventDisableTiming);
        cudaEventCreateWithFlags(&eWg,  cudaEventDisableTiming);
        cudaEventCreateWithFlags(&eWu,  cudaEventDisableTiming);
    }
};
static ForkCtx g_fork;

// ---------------------------------------------------------------------------
// PTX helpers (sm_80-baseline only)
__device__ __forceinline__ uint32_t smem_to_u32(const void* p) {
    uint32_t a;
    asm("{ .reg .u64 t; cvta.to.shared.u64 t, %1; cvt.u32.u64 %0, t; }"
        : "=r"(a) : "l"(p));
    return a;
}
__device__ __forceinline__ void cp_async16(uint32_t dst, const void* src) {
    asm volatile("cp.async.cg.shared.global [%0], [%1], 16;" :: "r"(dst), "l"(src));
}
#define CP_COMMIT() asm volatile("cp.async.commit_group;" ::: "memory")
#define CP_WAIT0()  asm volatile("cp.async.wait_group 0;" ::: "memory")

__device__ __forceinline__ void ldsm_x4(uint32_t* r, uint32_t addr) {
    asm volatile("ldmatrix.sync.aligned.m8n8.x4.shared.b16 {%0,%1,%2,%3}, [%4];"
        : "=r"(r[0]), "=r"(r[1]), "=r"(r[2]), "=r"(r[3]) : "r"(addr));
}
__device__ __forceinline__ void ldsm_x4_t(uint32_t* r, uint32_t addr) {
    asm volatile("ldmatrix.sync.aligned.m8n8.x4.trans.shared.b16 {%0,%1,%2,%3}, [%4];"
        : "=r"(r[0]), "=r"(r[1]), "=r"(r[2]), "=r"(r[3]) : "r"(addr));
}
__device__ __forceinline__ void mma16816(float* d, const uint32_t* a, const uint32_t* b) {
    asm volatile(
        "mma.sync.aligned.m16n8k16.row.col.f32.bf16.bf16.f32 "
        "{%0,%1,%2,%3}, {%4,%5,%6,%7}, {%8,%9}, {%0,%1,%2,%3};"
        : "+f"(d[0]), "+f"(d[1]), "+f"(d[2]), "+f"(d[3])
        : "r"(a[0]), "r"(a[1]), "r"(a[2]), "r"(a[3]), "r"(b[0]), "r"(b[1]));
}
__device__ __forceinline__ uint32_t pack_split2(float a, float b, uint32_t* lo) {
    __nv_bfloat16 h0 = __float2bfloat16(a);
    __nv_bfloat16 h1 = __float2bfloat16(b);
    __nv_bfloat16 l0 = __float2bfloat16(a - __bfloat162float(h0));
    __nv_bfloat16 l1 = __float2bfloat16(b - __bfloat162float(h1));
    uint32_t hi;
    ((__nv_bfloat16*)&hi)[0] = h0; ((__nv_bfloat16*)&hi)[1] = h1;
    ((__nv_bfloat16*)lo)[0] = l0;  ((__nv_bfloat16*)lo)[1] = l1;
    return hi;
}

// ---------------------------------------------------------------------------
// build X fp32 + Xh/Xl [n,bc] + transposed Bt1/Bt2 [bc,n]
__global__ void build_X_fused_kernel(const float* __restrict__ x,
                                     const float* __restrict__ st,
                                     float* __restrict__ X,
                                     __nv_bfloat16* __restrict__ Xh,
                                     __nv_bfloat16* __restrict__ Xl,
                                     __nv_bfloat16* __restrict__ hi,
                                     __nv_bfloat16* __restrict__ lo) {
    __shared__ float t[32][33];
    int bc0 = blockIdx.x * 32;
    int n0  = blockIdx.y * 32;
    int tx = threadIdx.x, ty = threadIdx.y;
#pragma unroll
    for (int i = 0; i < 4; i++) {
        int n = n0 + ty + 8*i;
        int bc = bc0 + tx;
        int c = bc & 127, b = bc >> 7;
        float v = (c < HH) ? x [(size_t)b * (NN*HH) + n*HH + c]
                           : st[(size_t)b * (NN*HH) + n*HH + (c - HH)];
        size_t o = (size_t)n * BCDIM + bc;
        X[o] = v;
        __nv_bfloat16 h = __float2bfloat16(v);
        Xh[o] = h;
        Xl[o] = __float2bfloat16(v - __bfloat162float(h));
        t[ty + 8*i][tx] = v;
    }
    __syncthreads();
#pragma unroll
    for (int i = 0; i < 4; i++) {
        float v = t[tx][ty + 8*i];
        __nv_bfloat16 h = __float2bfloat16(v);
        size_t o = (size_t)(bc0 + ty + 8*i) * NN + n0 + tx;
        hi[o] = h;
        lo[o] = __float2bfloat16(v - __bfloat162float(h));
    }
}

// ---------------------------------------------------------------------------
// A = softmax(relu(E E^T)) -> fp32 row-major only (fully coalesced)
__global__ void compute_A_kernel(const float* __restrict__ E,
                                 float* __restrict__ Af) {
    int i = blockIdx.x;
    int tid = threadIdx.x;
    __shared__ float Ei[ED];
    __shared__ float red[256];
    if (tid < ED) Ei[tid] = E[i*ED + tid];
    __syncthreads();

    float v[4];
    float vmax = 0.0f;
#pragma unroll
    for (int p = 0; p < 4; p++) {
        int j = tid + p * 256;
        const float4* Ej = (const float4*)(E + (size_t)j * ED);
        float4 e0 = Ej[0], e1 = Ej[1], e2 = Ej[2], e3 = Ej[3];
        float d = Ei[0]*e0.x + Ei[1]*e0.y + Ei[2]*e0.z + Ei[3]*e0.w
                + Ei[4]*e1.x + Ei[5]*e1.y + Ei[6]*e1.z + Ei[7]*e1.w
                + Ei[8]*e2.x + Ei[9]*e2.y + Ei[10]*e2.z + Ei[11]*e2.w
                + Ei[12]*e3.x + Ei[13]*e3.y + Ei[14]*e3.z + Ei[15]*e3.w;
        d = fmaxf(d, 0.0f);
        v[p] = d;
        vmax = fmaxf(vmax, d);
    }
    red[tid] = vmax; __syncthreads();
    for (int s = 128; s > 0; s >>= 1) {
        if (tid < s) red[tid] = fmaxf(red[tid], red[tid + s]);
        __syncthreads();
    }
    vmax = red[0];
    __syncthreads();
    float lsum = 0.0f;
#pragma unroll
    for (int p = 0; p < 4; p++) { v[p] = __expf(v[p] - vmax); lsum += v[p]; }
    red[tid] = lsum; __syncthreads();
    for (int s = 128; s > 0; s >>= 1) {
        if (tid < s) red[tid] += red[tid + s];
        __syncthreads();
    }
    float inv = 1.0f / red[0];
#pragma unroll
    for (int p = 0; p < 4; p++)
        Af[(size_t)i * NN + tid + p * 256] = v[p] * inv;
}

// ---------------------------------------------------------------------------
// split fp32 [NN,NN] -> row-major hi/lo AND transposed hi/lo (all coalesced)
__global__ void split_both_kernel(const float* __restrict__ src,
                                  __nv_bfloat16* __restrict__ hi,
                                  __nv_bfloat16* __restrict__ lo,
                                  __nv_bfloat16* __restrict__ thi,
                                  __nv_bfloat16* __restrict__ tlo) {
    __shared__ float t[32][33];
    int m0 = blockIdx.x * 32;   // col block
    int n0 = blockIdx.y * 32;   // row block
    int tx = threadIdx.x, ty = threadIdx.y;
#pragma unroll
    for (int i = 0; i < 4; i++) {
        int r = n0 + ty + 8*i;
        float v = src[(size_t)r * NN + m0 + tx];
        __nv_bfloat16 h = __float2bfloat16(v);
        size_t o = (size_t)r * NN + m0 + tx;
        hi[o] = h;
        lo[o] = __float2bfloat16(v - __bfloat162float(h));
        t[ty + 8*i][tx] = v;
    }
    __syncthreads();
#pragma unroll
    for (int i = 0; i < 4; i++) {
        float v = t[tx][ty + 8*i];
        __nv_bfloat16 h = __float2bfloat16(v);
        size_t o = (size_t)(m0 + ty + 8*i) * NN + n0 + tx;
        thi[o] = h;
        tlo[o] = __float2bfloat16(v - __bfloat162float(h));
    }
}

// ---------------------------------------------------------------------------
// transpose + split: src fp32 [NN, W] -> hi/lo bf16 [W, NN]
__global__ void transpose_split_kernel(const float* __restrict__ src,
                                       __nv_bfloat16* __restrict__ hi,
                                       __nv_bfloat16* __restrict__ lo, int W) {
    __shared__ float t[32][33];
    int m0 = blockIdx.x * 32;
    int n0 = blockIdx.y * 32;
    int tx = threadIdx.x, ty = threadIdx.y;
#pragma unroll
    for (int i = 0; i < 4; i++)
        t[ty + 8*i][tx] = src[(size_t)(n0 + ty + 8*i) * W + m0 + tx];
    __syncthreads();
#pragma unroll
    for (int i = 0; i < 4; i++) {
        float v = t[tx][ty + 8*i];
        __nv_bfloat16 h = __float2bfloat16(v);
        size_t o = (size_t)(m0 + ty + 8*i) * NN + n0 + tx;
        hi[o] = h;
        lo[o] = __float2bfloat16(v - __bfloat162float(h));
    }
}

// ---------------------------------------------------------------------------
// Big bf16x3 GEMM, 3-stage cp.async pipeline, one barrier per K-chunk.
// acc = (Ahi+Alo) @ (Bhi+Blo)^T.
// Epilogue: if block_row >= comb_start, acc = 2*acc - Xref[row-comb_start];
// always written as bf16 hi/lo split to Ch/Cl.
#define GSTRIDE 144
#define HALF_BYTES (128*GSTRIDE)
#define STAGE_BYTES (4*HALF_BYTES)
#define GEMM_SMEM (3*STAGE_BYTES)   /* 221184 bytes, 3 stages */

__global__ __launch_bounds__(256, 1)
void mma_gemm_kernel(const __nv_bfloat16* __restrict__ Ahi,
                     const __nv_bfloat16* __restrict__ Alo,
                     const __nv_bfloat16* __restrict__ Bhi,
                     const __nv_bfloat16* __restrict__ Blo,
                     __nv_bfloat16* __restrict__ Ch,
                     __nv_bfloat16* __restrict__ Cl,
                     const float* __restrict__ Xref, int comb_start,
                     int M, int N, int K) {
    extern __shared__ char smem[];
    uint32_t sb = smem_to_u32(smem);
    int tid = threadIdx.x;
    int lane = tid & 31, wid = tid >> 5;
    int wm = (wid >> 1) * 32;
    int wn = (wid & 1) * 64;
    int block_row = blockIdx.y * 128;
    int block_col = blockIdx.x * 128;

    const char* gA0 = (const char*)(Ahi + (size_t)block_row * K);
    const char* gA1 = (const char*)(Alo + (size_t)block_row * K);
    const char* gB0 = (const char*)(Bhi + (size_t)block_col * K);
    const char* gB1 = (const char*)(Blo + (size_t)block_col * K);

    int lr_ = tid >> 3;
    int lc_ = (tid & 7) * 16;

    float acc[2][8][4];
#pragma unroll
    for (int mt = 0; mt < 2; mt++)
#pragma unroll
        for (int nt = 0; nt < 8; nt++)
#pragma unroll
            for (int q = 0; q < 4; q++) acc[mt][nt][q] = 0.0f;

    int g = lane >> 3;
    int lr8 = lane & 7;
    int a_row = wm + (g & 1) * 8 + lr8;
    int a_kc  = (g >> 1) * 8;
    int b_row = wn + (g >> 1) * 8 + lr8;
    int b_kc  = (g & 1) * 8;

    int nstages = K >> 6;

    auto load_stage = [&](int st, int kt) {
        uint32_t base = sb + st * STAGE_BYTES;
        size_t k0b = (size_t)(kt * 64) * 2;
#pragma unroll
        for (int q = 0; q < 4; q++) {
            int r = lr_ + q * 32;
            uint32_t so = (uint32_t)(r * GSTRIDE + lc_);
            size_t go = (size_t)r * (K * 2) + k0b + lc_;
            cp_async16(base + 0*HALF_BYTES + so, gA0 + go);
            cp_async16(base + 1*HALF_BYTES + so, gA1 + go);
            cp_async16(base + 2*HALF_BYTES + so, gB0 + go);
            cp_async16(base + 3*HALF_BYTES + so, gB1 + go);
        }
        CP_COMMIT();
    };

    // prologue: two stages in flight
    load_stage(0, 0);
    if (nstages > 1) load_stage(1, 1);

    for (int kt = 0; kt < nstages; kt++) {
        int st = kt % 3;
        if (kt + 1 < nstages) {
            asm volatile("cp.async.wait_group 1;" ::: "memory");
        } else {
            CP_WAIT0();
        }
        __syncthreads();
        if (kt + 2 < nstages) load_stage((kt + 2) % 3, kt + 2);

        uint32_t aHiB = sb + st * STAGE_BYTES;
        uint32_t aLoB = aHiB + HALF_BYTES;
        uint32_t bHiB = aLoB + HALF_BYTES;
        uint32_t bLoB = bHiB + HALF_BYTES;

#pragma unroll
        for (int ks = 0; ks < 4; ks++) {
            int kc = ks * 16;
            uint32_t ahi[2][4], alo[2][4];
#pragma unroll
            for (int mt = 0; mt < 2; mt++) {
                uint32_t ad = (uint32_t)((a_row + mt*16) * GSTRIDE + (kc + a_kc) * 2);
                ldsm_x4(ahi[mt], aHiB + ad);
                ldsm_x4(alo[mt], aLoB + ad);
            }
            uint32_t bhi[8][2], blo[8][2];
#pragma unroll
            for (int np = 0; np < 4; np++) {
                uint32_t bd = (uint32_t)((b_row + np*16) * GSTRIDE + (kc + b_kc) * 2);
                uint32_t t[4];
                ldsm_x4(t, bHiB + bd);
                bhi[2*np][0] = t[0]; bhi[2*np][1] = t[1];
                bhi[2*np+1][0] = t[2]; bhi[2*np+1][1] = t[3];
                ldsm_x4(t, bLoB + bd);
                blo[2*np][0] = t[0]; blo[2*np][1] = t[1];
                blo[2*np+1][0] = t[2]; blo[2*np+1][1] = t[3];
            }
#pragma unroll
            for (int mt = 0; mt < 2; mt++)
#pragma unroll
                for (int nt = 0; nt < 8; nt++) {
                    mma16816(acc[mt][nt], ahi[mt], bhi[nt]);
                    mma16816(acc[mt][nt], ahi[mt], blo[nt]);
                    mma16816(acc[mt][nt], alo[mt], bhi[nt]);
                }
        }
    }

    int erow = lane >> 2, ecol = (lane & 3) * 2;
    bool comb = (block_row >= comb_start);
#pragma unroll
    for (int mt = 0; mt < 2; mt++) {
#pragma unroll
        for (int nt = 0; nt < 8; nt++) {
            size_t cc = (size_t)block_col + wn + nt*8 + ecol;
#pragma unroll
            for (int h = 0; h < 2; h++) {
                size_t row = (size_t)block_row + wm + mt*16 + erow + h*8;
                float v0 = acc[mt][nt][h*2+0];
                float v1 = acc[mt][nt][h*2+1];
                if (comb) {
                    const float* xr = Xref + (row - comb_start) * N + cc;
                    v0 = 2.0f*v0 - xr[0];
                    v1 = 2.0f*v1 - xr[1];
                }
                uint32_t lo;
                uint32_t hi = pack_split2(v0, v1, &lo);
                *(uint32_t*)(Ch + row * N + cc) = hi;
                *(uint32_t*)(Cl + row * N + cc) = lo;
            }
        }
    }
}

// ---------------------------------------------------------------------------
// W[n,:] = sum_e E[n,e] * Wp[e,:], output bf16 hi/lo (4-node groups: low regs)
__global__ __launch_bounds__(256)
void build_W_kernel(const float* __restrict__ Wp,
                    const float* __restrict__ E,
                    __nv_bfloat16* __restrict__ Wh,
                    __nv_bfloat16* __restrict__ Wl, int TC) {
    int ng = blockIdx.y;
    int cbase = blockIdx.x * 1024;
    __shared__ float Es[16][16];
    {
        int nn = threadIdx.x >> 4, e = threadIdx.x & 15;
        if (threadIdx.x < 256) Es[nn][e] = E[(ng * 16 + nn) * ED + e];
    }
    __syncthreads();
#pragma unroll 1
    for (int cc = 0; cc < 1024; cc += 256) {
        int c = cbase + cc + threadIdx.x;
        float wp[16];
#pragma unroll
        for (int e = 0; e < 16; e++) wp[e] = Wp[(size_t)e * TC + c];
#pragma unroll 1
        for (int nn0 = 0; nn0 < 16; nn0 += 4) {
#pragma unroll
            for (int k = 0; k < 4; k++) {
                int nn = nn0 + k;
                float a = 0.0f;
#pragma unroll
                for (int e = 0; e < 16; e++) a += Es[nn][e] * wp[e];
                __nv_bfloat16 h = __float2bfloat16(a);
                size_t o = (size_t)(ng * 16 + nn) * TC + c;
                Wh[o] = h;
                Wl[o] = __float2bfloat16(a - __bfloat162float(h));
            }
        }
    }
}

// ---------------------------------------------------------------------------
// Per-node GATE: pure cp.async -> ldsm -> mma (all operands pre-split bf16).
// smem: XH +0 (64x144B), XL +9216, WH +18432 (64x272B), WL +35840, bias +53248.
#define GATE_SMEM 53760
__global__ __launch_bounds__(256)
void pernode_gate_mma(const float* __restrict__ X,
                      const __nv_bfloat16* __restrict__ Xh,
                      const __nv_bfloat16* __restrict__ Xl,
                      const __nv_bfloat16* __restrict__ Yh,
                      const __nv_bfloat16* __restrict__ Yl,
                      const __nv_bfloat16* __restrict__ Wh,
                      const __nv_bfloat16* __restrict__ Wl,
                      const float* __restrict__ E, const float* __restrict__ bpool,
                      float* __restrict__ X2s,
                      __nv_bfloat16* __restrict__ X2sh,
                      __nv_bfloat16* __restrict__ X2sl,
                      float* __restrict__ R) {
    extern __shared__ char sm[];
    uint32_t sb = smem_to_u32(sm);
    float* bias = (float*)(sm + 53248);
    int n = blockIdx.x;
    int tid = threadIdx.x, lane = tid & 31, wid = tid >> 5;

    if (tid < 128) {
        float a = 0.0f;
#pragma unroll
        for (int e = 0; e < 16; e++) a += E[n*ED + e] * bpool[e*128 + tid];
        bias[tid] = a;
    }

    const float* Xn = X + (size_t)n * BCDIM;
    const __nv_bfloat16* gWh = Wh + (size_t)n * (3*CC*CC);
    const __nv_bfloat16* gWl = Wl + (size_t)n * (3*CC*CC);

    const __nv_bfloat16* srcH[6];
    const __nv_bfloat16* srcL[6];
    {
        const __nv_bfloat16* xh = Xh + (size_t)n * BCDIM;
        const __nv_bfloat16* xl = Xl + (size_t)n * BCDIM;
        const __nv_bfloat16* y1h = Yh + (size_t)n * BCDIM;
        const __nv_bfloat16* y1l = Yl + (size_t)n * BCDIM;
        const __nv_bfloat16* y2h = Yh + (size_t)(NN + n) * BCDIM;
        const __nv_bfloat16* y2l = Yl + (size_t)(NN + n) * BCDIM;
        srcH[0] = xh;      srcL[0] = xl;
        srcH[1] = xh + 64; srcL[1] = xl + 64;
        srcH[2] = y1h;     srcL[2] = y1l;
        srcH[3] = y1h + 64; srcL[3] = y1l + 64;
        srcH[4] = y2h;     srcL[4] = y2l;
        srcH[5] = y2h + 64; srcL[5] = y2l + 64;
    }

    int wm = (wid >> 1) * 16, wn = (wid & 1) * 64;
    int g = lane >> 3, lr8 = lane & 7;

    float acc[8][4];
#pragma unroll
    for (int nt = 0; nt < 8; nt++)
#pragma unroll
        for (int q = 0; q < 4; q++) acc[nt][q] = 0.0f;

    for (int ck = 0; ck < 6; ck++) {
        {
            int kc0 = ck * 64;
#pragma unroll
            for (int q = 0; q < 4; q++) {
                int m = tid + q * 256;
                int kr = m >> 4, o8 = m & 15;
                uint32_t so = (uint32_t)(kr * 272 + o8 * 16);
                size_t eoff = (size_t)(kc0 + kr) * 128 + o8 * 8;
                cp_async16(sb + 18432 + so, gWh + eoff);
                cp_async16(sb + 35840 + so, gWl + eoff);
            }
        }
        {
            const __nv_bfloat16* ph = srcH[ck];
            const __nv_bfloat16* pl = srcL[ck];
#pragma unroll
            for (int q = 0; q < 2; q++) {
                int m = tid + q * 256;
                int r = m >> 3, c8 = m & 7;
                uint32_t so = (uint32_t)(r * 144 + c8 * 16);
                size_t eoff = (size_t)r * 128 + c8 * 8;
                cp_async16(sb + so, ph + eoff);
                cp_async16(sb + 9216 + so, pl + eoff);
            }
        }
        CP_COMMIT();
        CP_WAIT0();
        __syncthreads();

#pragma unroll
        for (int ks = 0; ks < 4; ks++) {
            uint32_t ahi[4], alo[4];
            uint32_t aad = (uint32_t)((wm + (g&1)*8 + lr8) * 144
                                      + (ks*16 + (g>>1)*8) * 2);
            ldsm_x4(ahi, sb + aad);
            ldsm_x4(alo, sb + 9216 + aad);
#pragma unroll
            for (int np = 0; np < 4; np++) {
                uint32_t bad = (uint32_t)((ks*16 + (g&1)*8 + lr8) * 272
                                          + (wn + np*16 + (g>>1)*8) * 2);
                uint32_t th[4], tl[4];
                ldsm_x4_t(th, sb + 18432 + bad);
                ldsm_x4_t(tl, sb + 35840 + bad);
                uint32_t b0h[2] = {th[0], th[1]}, b1h[2] = {th[2], th[3]};
                uint32_t b0l[2] = {tl[0], tl[1]}, b1l[2] = {tl[2], tl[3]};
                mma16816(acc[2*np],   ahi, b0h);
                mma16816(acc[2*np],   ahi, b0l);
                mma16816(acc[2*np],   alo, b0h);
                mma16816(acc[2*np+1], ahi, b1h);
                mma16816(acc[2*np+1], ahi, b1l);
                mma16816(acc[2*np+1], alo, b1h);
            }
        }
        __syncthreads();
    }

    float* X2sn = X2s + (size_t)n * SHDIM;
    __nv_bfloat16* X2shn = X2sh + (size_t)n * SHDIM;
    __nv_bfloat16* X2sln = X2sl + (size_t)n * SHDIM;
    float* Rn = R + (size_t)n * SHDIM;
    int erow = lane >> 2, ecol = (lane & 3) * 2;
    bool isz = ((wid & 1) == 0);
#pragma unroll
    for (int nt = 0; nt < 8; nt++) {
        int c = wn + nt*8 + ecol;
        float b0 = bias[c], b1 = bias[c+1];
#pragma unroll
        for (int h = 0; h < 2; h++) {
            int b = wm + erow + h*8;
            float s0 = 1.0f / (1.0f + __expf(-(acc[nt][h*2+0] + b0)));
            float s1 = 1.0f / (1.0f + __expf(-(acc[nt][h*2+1] + b1)));
            if (isz) {
                float2 st = *(const float2*)(Xn + b*128 + 64 + c);
                float z0 = s0 * st.x, z1 = s1 * st.y;
                *(float2*)(X2sn + b*64 + c) = make_float2(z0, z1);
                uint32_t lo;
                uint32_t hi = pack_split2(z0, z1, &lo);
                *(uint32_t*)(X2shn + b*64 + c) = hi;
                *(uint32_t*)(X2sln + b*64 + c) = lo;
            } else {
                *(float2*)(Rn + b*64 + (c - 64)) = make_float2(s0, s1);
            }
        }
    }
}

// ---------------------------------------------------------------------------
// Per-node UPDATE: pure cp.async -> ldsm -> mma + GRU combine.
// smem: XH +0, XL +9216, WH +18432 (64x144B), WL +27648, bias +36864.
#define UPD_SMEM 37120
__global__ __launch_bounds__(256)
void pernode_upd_mma(const float* __restrict__ X,
                     const __nv_bfloat16* __restrict__ Xh,
                     const __nv_bfloat16* __restrict__ Xl,
                     const __nv_bfloat16* __restrict__ Yh,
                     const __nv_bfloat16* __restrict__ Yl,
                     const __nv_bfloat16* __restrict__ X2sh,
                     const __nv_bfloat16* __restrict__ X2sl,
                     const __nv_bfloat16* __restrict__ Ysh,
                     const __nv_bfloat16* __restrict__ Ysl,
                     const __nv_bfloat16* __restrict__ Wh,
                     const __nv_bfloat16* __restrict__ Wl,
                     const float* __restrict__ E, const float* __restrict__ bpool,
                     const float* __restrict__ R, float* __restrict__ out) {
    extern __shared__ char sm[];
    uint32_t sb = smem_to_u32(sm);
    float* bias = (float*)(sm + 36864);
    int n = blockIdx.x;
    int tid = threadIdx.x, lane = tid & 31, wid = tid >> 5;

    if (tid < 64) {
        float a = 0.0f;
#pragma unroll
        for (int e = 0; e < 16; e++) a += E[n*ED + e] * bpool[e*64 + tid];
        bias[tid] = a;
    }

    const float* Xn = X + (size_t)n * BCDIM;
    const __nv_bfloat16* gWh = Wh + (size_t)n * (3*CC*HH);
    const __nv_bfloat16* gWl = Wl + (size_t)n * (3*CC*HH);

    const __nv_bfloat16* srcH[6];
    const __nv_bfloat16* srcL[6];
    int rstr[6];
    {
        srcH[0] = Xh   + (size_t)n * BCDIM;        srcL[0] = Xl   + (size_t)n * BCDIM;        rstr[0] = 128;
        srcH[1] = X2sh + (size_t)n * SHDIM;        srcL[1] = X2sl + (size_t)n * SHDIM;        rstr[1] = 64;
        srcH[2] = Yh   + (size_t)n * BCDIM;        srcL[2] = Yl   + (size_t)n * BCDIM;        rstr[2] = 128;
        srcH[3] = Ysh  + (size_t)n * SHDIM;        srcL[3] = Ysl  + (size_t)n * SHDIM;        rstr[3] = 64;
        srcH[4] = Yh   + (size_t)(NN+n) * BCDIM;   srcL[4] = Yl   + (size_t)(NN+n) * BCDIM;   rstr[4] = 128;
        srcH[5] = Ysh  + (size_t)(NN+n) * SHDIM;   srcL[5] = Ysl  + (size_t)(NN+n) * SHDIM;   rstr[5] = 64;
    }

    int wm = (wid >> 1) * 16, wn = (wid & 1) * 32;
    int g = lane >> 3, lr8 = lane & 7;

    float acc[4][4];
#pragma unroll
    for (int nt = 0; nt < 4; nt++)
#pragma unroll
        for (int q = 0; q < 4; q++) acc[nt][q] = 0.0f;

    for (int ck = 0; ck < 6; ck++) {
        {
            int kc0 = ck * 64;
#pragma unroll
            for (int q = 0; q < 2; q++) {
                int m = tid + q * 256;
                int kr = m >> 3, o8 = m & 7;
                uint32_t so = (uint32_t)(kr * 144 + o8 * 16);
                size_t eoff = (size_t)(kc0 + kr) * 64 + o8 * 8;
                cp_async16(sb + 18432 + so, gWh + eoff);
                cp_async16(sb + 27648 + so, gWl + eoff);
            }
        }
        {
            const __nv_bfloat16* ph = srcH[ck];
            const __nv_bfloat16* pl = srcL[ck];
            int str = rstr[ck];
#pragma unroll
            for (int q = 0; q < 2; q++) {
                int m = tid + q * 256;
                int r = m >> 3, c8 = m & 7;
                uint32_t so = (uint32_t)(r * 144 + c8 * 16);
                size_t eoff = (size_t)r * str + c8 * 8;
                cp_async16(sb + so, ph + eoff);
                cp_async16(sb + 9216 + so, pl + eoff);
            }
        }
        CP_COMMIT();
        CP_WAIT0();
        __syncthreads();

#pragma unroll
        for (int ks = 0; ks < 4; ks++) {
            uint32_t ahi[4], alo[4];
            uint32_t aad = (uint32_t)((wm + (g&1)*8 + lr8) * 144
                                      + (ks*16 + (g>>1)*8) * 2);
            ldsm_x4(ahi, sb + aad);
            ldsm_x4(alo, sb + 9216 + aad);
#pragma unroll
            for (int np = 0; np < 2; np++) {
                uint32_t bad = (uint32_t)((ks*16 + (g&1)*8 + lr8) * 144
                                          + (wn + np*16 + (g>>1)*8) * 2);
                uint32_t th[4], tl[4];
                ldsm_x4_t(th, sb + 18432 + bad);
                ldsm_x4_t(tl, sb + 27648 + bad);
                uint32_t b0h[2] = {th[0], th[1]}, b1h[2] = {th[2], th[3]};
                uint32_t b0l[2] = {tl[0], tl[1]}, b1l[2] = {tl[2], tl[3]};
                mma16816(acc[2*np],   ahi, b0h);
                mma16816(acc[2*np],   ahi, b0l);
                mma16816(acc[2*np],   alo, b0h);
                mma16816(acc[2*np+1], ahi, b1h);
                mma16816(acc[2*np+1], ahi, b1l);
                mma16816(acc[2*np+1], alo, b1h);
            }
        }
        __syncthreads();
    }

    const float* Rn = R + (size_t)n * SHDIM;
    int erow = lane >> 2, ecol = (lane & 3) * 2;
#pragma unroll
    for (int nt = 0; nt < 4; nt++) {
        int c = wn + nt*8 + ecol;
        float b0 = bias[c], b1 = bias[c+1];
#pragma unroll
        for (int h = 0; h < 2; h++) {
            int b = wm + erow + h*8;
            float hc0 = tanhf(acc[nt][h*2+0] + b0);
            float hc1 = tanhf(acc[nt][h*2+1] + b1);
            float2 r  = *(const float2*)(Rn + b*64 + c);
            float2 st = *(const float2*)(Xn + b*128 + 64 + c);
            float o0 = r.x * st.x + (1.0f - r.x) * hc0;
            float o1 = r.y * st.y + (1.0f - r.y) * hc1;
            *(float2*)(out + (size_t)b * (NN*HH) + n*HH + c) = make_float2(o0, o1);
        }
    }
}

// ---------------------------------------------------------------------------
extern "C" void kernel_launch(void* const* d_in, const int* in_sizes, int n_in,
                              void* d_out, int out_size) {
    const float* x     = (const float*)d_in[0];
    const float* state = (const float*)d_in[1];
    const float* E     = (const float*)d_in[2];
    const float* gWp   = (const float*)d_in[3];
    const float* gbp   = (const float*)d_in[4];
    const float* uWp   = (const float*)d_in[5];
    const float* ubp   = (const float*)d_in[6];
    float* out = (float*)d_out;

    float *X, *X2s, *R, *Af;
    __nv_bfloat16 *Xh, *Xl, *Yh, *Yl, *X2sh, *X2sl, *Ysh, *Ysl;
    __nv_bfloat16 *Ah, *Al, *Ath, *Atl, *Bt1, *Bt2, *Wh, *Wl, *Whu, *Wlu;
    cudaGetSymbolAddress((void**)&X,    g_X);
    cudaGetSymbolAddress((void**)&X2s,  g_X2s);
    cudaGetSymbolAddress((void**)&R,    g_R);
    cudaGetSymbolAddress((void**)&Af,   g_Af);
    cudaGetSymbolAddress((void**)&Xh,   g_Xh);
    cudaGetSymbolAddress((void**)&Xl,   g_Xl);
    cudaGetSymbolAddress((void**)&Yh,   g_Yh);
    cudaGetSymbolAddress((void**)&Yl,   g_Yl);
    cudaGetSymbolAddress((void**)&X2sh, g_X2sh);
    cudaGetSymbolAddress((void**)&X2sl, g_X2sl);
    cudaGetSymbolAddress((void**)&Ysh,  g_Ysh);
    cudaGetSymbolAddress((void**)&Ysl,  g_Ysl);
    cudaGetSymbolAddress((void**)&Ah,   g_Ah);
    cudaGetSymbolAddress((void**)&Al,   g_Al);
    cudaGetSymbolAddress((void**)&Ath,  g_Ath);
    cudaGetSymbolAddress((void**)&Atl,  g_Atl);
    cudaGetSymbolAddress((void**)&Bt1,  g_Bt1);
    cudaGetSymbolAddress((void**)&Bt2,  g_Bt2);
    cudaGetSymbolAddress((void**)&Wh,   g_Wh);
    cudaGetSymbolAddress((void**)&Wl,   g_Wl);
    cudaGetSymbolAddress((void**)&Whu,  g_Whu);
    cudaGetSymbolAddress((void**)&Wlu,  g_Wlu);

    cudaFuncSetAttribute(mma_gemm_kernel,
                         cudaFuncAttributeMaxDynamicSharedMemorySize, GEMM_SMEM);
    cudaFuncSetAttribute(pernode_gate_mma,
                         cudaFuncAttributeMaxDynamicSharedMemorySize, GATE_SMEM);
    cudaFuncSetAttribute(pernode_upd_mma,
                         cudaFuncAttributeMaxDynamicSharedMemorySize, UPD_SMEM);

    // fork side branches off the capture-origin stream
    cudaEventRecord(g_fork.fork, 0);
    cudaStreamWaitEvent(g_fork.s1, g_fork.fork, 0);
    cudaStreamWaitEvent(g_fork.s2, g_fork.fork, 0);

    // --- branch s1: softmax A (fp32, coalesced) -> split both -> A^2 GEMM
    compute_A_kernel<<<NN, 256, 0, g_fork.s1>>>(E, Af);
    split_both_kernel<<<dim3(NN/32, NN/32), dim3(32, 8), 0, g_fork.s1>>>(
        Af, Ah, Al, Ath, Atl);
    cudaEventRecord(g_fork.eA0, g_fork.s1);
    mma_gemm_kernel<<<dim3(NN/128, NN/128), 256, GEMM_SMEM, g_fork.s1>>>(
        Ah, Al, Ath, Atl, Ah + (size_t)NN*NN, Al + (size_t)NN*NN,
        nullptr, 1 << 30, NN, NN, NN);
    cudaEventRecord(g_fork.eA, g_fork.s1);

    // --- branch s2: per-node weight pools
    build_W_kernel<<<dim3(48, 64), 256, 0, g_fork.s2>>>(gWp, E, Wh, Wl, 3*CC*CC);
    cudaEventRecord(g_fork.eWg, g_fork.s2);
    build_W_kernel<<<dim3(24, 64), 256, 0, g_fork.s2>>>(uWp, E, Whu, Wlu, 3*CC*HH);
    cudaEventRecord(g_fork.eWu, g_fork.s2);

    // --- main branch (stream 0)
    build_X_fused_kernel<<<dim3(BCDIM/32, NN/32), dim3(32, 8)>>>(
        x, state, X, Xh, Xl, Bt1, Bt2);

    // GEMM1 A-half: Y rows [0,NN) = A @ X^T — needs only split A (eA0) + Bt
    cudaStreamWaitEvent(0, g_fork.eA0, 0);
    mma_gemm_kernel<<<dim3(BCDIM/128, NN/128), 256, GEMM_SMEM>>>(
        Ah, Al, Bt1, Bt2, Yh, Yl, nullptr, 1 << 30, NN, BCDIM, NN);
    // GEMM1 A^2-half: rows [NN,2NN) with 2*acc - X combine — needs A^2 (eA)
    cudaStreamWaitEvent(0, g_fork.eA, 0);
    mma_gemm_kernel<<<dim3(BCDIM/128, NN/128), 256, GEMM_SMEM>>>(
        Ah + (size_t)NN*NN, Al + (size_t)NN*NN, Bt1, Bt2,
        Yh + (size_t)NN*BCDIM, Yl + (size_t)NN*BCDIM, X, 0, NN, BCDIM, NN);

    cudaStreamWaitEvent(0, g_fork.eWg, 0);
    pernode_gate_mma<<<NN, 256, GATE_SMEM>>>(
        X, Xh, Xl, Yh, Yl, Wh, Wl, E, gbp, X2s, X2sh, X2sl, R);

    // GEMM2: [A;A^2] @ X2s^T, rows >= NN combined with X2s; hi/lo out
    transpose_split_kernel<<<dim3(SHDIM/32, NN/32), dim3(32, 8)>>>(X2s, Bt1, Bt2, SHDIM);
    mma_gemm_kernel<<<dim3(SHDIM/128, 2*NN/128), 256, GEMM_SMEM>>>(
        Ah, Al, Bt1, Bt2, Ysh, Ysl, X2s, NN, 2*NN, SHDIM, NN);

    cudaStreamWaitEvent(0, g_fork.eWu, 0);
    pernode_upd_mma<<<NN, 256, UPD_SMEM>>>(
        X, Xh, Xl, Yh, Yl, X2sh, X2sl, Ysh, Ysl, Whu, Wlu, E, ubp, R, out);
}